// round 15
// baseline (speedup 1.0000x reference)
#include <cuda_runtime.h>
#include <cuda_bf16.h>
#include <math.h>
#include <stdint.h>

#define DM 768
#define BB 32
#define SS 512
#define MR (BB*SS)          // 16384 rows
#define NEL (MR*DM)         // 12582912

typedef __nv_bfloat16 bf16;

// ======================= helpers =======================
__device__ __forceinline__ uint32_t smem_u32(const void* p) {
    uint32_t a;
    asm("{ .reg .u64 t; cvta.to.shared.u64 t, %1; cvt.u32.u64 %0, t; }" : "=r"(a) : "l"(p));
    return a;
}
__device__ __forceinline__ void cp_async16(uint32_t dst, const void* src) {
    asm volatile("cp.async.cg.shared.global [%0],[%1],16;" :: "r"(dst), "l"(src));
}
__device__ __forceinline__ void cp_commit() { asm volatile("cp.async.commit_group;"); }
template <int N>
__device__ __forceinline__ void cp_wait() { asm volatile("cp.async.wait_group %0;" :: "n"(N)); }
__device__ __forceinline__ void ldmx4(uint32_t& a0, uint32_t& a1, uint32_t& a2, uint32_t& a3, uint32_t addr) {
    asm volatile("ldmatrix.sync.aligned.m8n8.x4.shared.b16 {%0,%1,%2,%3},[%4];"
                 : "=r"(a0), "=r"(a1), "=r"(a2), "=r"(a3) : "r"(addr));
}
__device__ __forceinline__ void mma16816(float* c, uint32_t a0, uint32_t a1, uint32_t a2, uint32_t a3,
                                         uint32_t b0, uint32_t b1) {
    asm volatile("mma.sync.aligned.m16n8k16.row.col.f32.bf16.bf16.f32 "
                 "{%0,%1,%2,%3},{%4,%5,%6,%7},{%8,%9},{%0,%1,%2,%3};"
                 : "+f"(c[0]), "+f"(c[1]), "+f"(c[2]), "+f"(c[3])
                 : "r"(a0), "r"(a1), "r"(a2), "r"(a3), "r"(b0), "r"(b1));
}
__device__ __forceinline__ uint32_t swz(int row, int chunk) {
    return (uint32_t)(row * 64 + ((chunk ^ ((row >> 1) & 3)) << 4));
}
__device__ __forceinline__ void store_split2(bf16* Oh, bf16* Ol, size_t idx, float a, float b) {
    bf16 ha = __float2bfloat16(a);
    bf16 hb = __float2bfloat16(b);
    __nv_bfloat162 hh; hh.x = ha; hh.y = hb;
    __nv_bfloat162 ll;
    ll.x = __float2bfloat16(a - __bfloat162float(ha));
    ll.y = __float2bfloat16(b - __bfloat162float(hb));
    *(__nv_bfloat162*)(Oh + idx) = hh;
    *(__nv_bfloat162*)(Ol + idx) = ll;
}
__device__ __forceinline__ void split1(float x, bf16* h, bf16* l, size_t idx) {
    bf16 hh = __float2bfloat16(x);
    h[idx] = hh;
    l[idx] = __float2bfloat16(x - __bfloat162float(hh));
}

// ======================= scratch =======================
static __device__ float g_sc[67108864];
static __device__ float g_F1[NEL];
static __device__ float g_F2[NEL];
static __device__ float g_F3[NEL];

#define WSZ (768*768)
static __device__ bf16 g_wth[12 * WSZ];
static __device__ bf16 g_wtl[12 * WSZ];
static __device__ bf16 g_cth[768 * 1536];
static __device__ bf16 g_ctl[768 * 1536];

static __device__ bf16 g_spt_h[NEL], g_spt_l[NEL];
static __device__ bf16 g_sev_h[NEL], g_sev_l[NEL];
static __device__ bf16 g_sea_h[NEL], g_sea_l[NEL];
static __device__ bf16 g_sq_h[NEL],  g_sq_l[NEL];
static __device__ bf16 g_sk_h[NEL],  g_sk_l[NEL];
static __device__ bf16 g_svt_h[NEL + 65536], g_svt_l[NEL + 65536];
static __device__ bf16 g_sq2_h[NEL],  g_sq2_l[NEL];
static __device__ bf16 g_sk2_h[NEL],  g_sk2_l[NEL];
static __device__ bf16 g_svt2_h[NEL + 65536], g_svt2_l[NEL + 65536];
static __device__ bf16 g_sp_h[67108864], g_sp_l[67108864];
static __device__ bf16 g_s1_h[NEL], g_s1_l[NEL];
static __device__ bf16 g_s2_h[NEL], g_s2_l[NEL];
static __device__ bf16 g_s3_h[NEL], g_s3_l[NEL];
static __device__ bf16 g_s4_h[NEL], g_s4_l[NEL];
static __device__ bf16 g_c1_h[NEL], g_c1_l[NEL];
static __device__ bf16 g_c2_h[NEL], g_c2_l[NEL];
static __device__ bf16 g_c3_h[NEL], g_c3_l[NEL];   // dedicated: split(F1), survives stage 2

// ======================= elementwise =======================
// z=0: split(text); z=1: embed+split visual; z=2: embed+split acoustic
__global__ void __launch_bounds__(256) prep3_kernel(
    const float* __restrict__ text,
    const float* __restrict__ vtab, const float* __restrict__ atab,
    const int* __restrict__ vid, const int* __restrict__ aid,
    bf16* __restrict__ t_h, bf16* __restrict__ t_l,
    bf16* __restrict__ v_h, bf16* __restrict__ v_l,
    bf16* __restrict__ a_h, bf16* __restrict__ a_l)
{
    int i = blockIdx.x * 256 + threadIdx.x;
    if (i >= NEL) return;
    int z = blockIdx.y;
    if (z == 0) {
        split1(text[i], t_h, t_l, i);
    } else {
        int row = i / DM;
        int d = i - row * DM;
        if (z == 1) split1(vtab[(size_t)vid[row] * DM + d], v_h, v_l, i);
        else        split1(atab[(size_t)aid[row] * DM + d], a_h, a_l, i);
    }
}

// batched transpose+split of 12 square weights
__global__ void __launch_bounds__(256) wsplit12_kernel(
    const float* __restrict__ s0, const float* __restrict__ s1, const float* __restrict__ s2,
    const float* __restrict__ s3, const float* __restrict__ s4, const float* __restrict__ s5,
    const float* __restrict__ s6, const float* __restrict__ s7, const float* __restrict__ s8,
    const float* __restrict__ s9, const float* __restrict__ s10, const float* __restrict__ s11,
    bf16* __restrict__ Th, bf16* __restrict__ Tl)
{
    const float* srcs[12] = { s0, s1, s2, s3, s4, s5, s6, s7, s8, s9, s10, s11 };
    const float* W = srcs[blockIdx.z];
    bf16* th = Th + (size_t)blockIdx.z * WSZ;
    bf16* tl = Tl + (size_t)blockIdx.z * WSZ;

    __shared__ float t[32][33];
    int k0 = blockIdx.x * 32, n0 = blockIdx.y * 32;
    int tx = threadIdx.x & 31, ty = threadIdx.x >> 5;
    #pragma unroll
    for (int i = 0; i < 32; i += 8)
        t[ty + i][tx] = W[(size_t)(k0 + ty + i) * 768 + n0 + tx];
    __syncthreads();
    #pragma unroll
    for (int i = 0; i < 32; i += 8)
        split1(t[tx][ty + i], th, tl, (size_t)(n0 + ty + i) * 768 + k0 + tx);
}

// transpose + split for cat weight: W [K,768] -> T_hi/lo [768,K]
__global__ void __launch_bounds__(256) wsplit_kernel(
    const float* __restrict__ W, bf16* __restrict__ Th, bf16* __restrict__ Tl, int K)
{
    __shared__ float t[32][33];
    int k0 = blockIdx.x * 32, n0 = blockIdx.y * 32;
    int tx = threadIdx.x & 31, ty = threadIdx.x >> 5;
    #pragma unroll
    for (int i = 0; i < 32; i += 8)
        t[ty + i][tx] = W[(size_t)(k0 + ty + i) * 768 + n0 + tx];
    __syncthreads();
    #pragma unroll
    for (int i = 0; i < 32; i += 8)
        split1(t[tx][ty + i], Th, Tl, (size_t)(n0 + ty + i) * K + k0 + tx);
}

__global__ void __launch_bounds__(256) softmax_split_kernel(
    const float* __restrict__ x, bf16* __restrict__ ph, bf16* __restrict__ pl)
{
    __shared__ float shm[8];
    __shared__ float shs[8];
    size_t row = blockIdx.x;
    const float* p = x + row * 512;
    int t = threadIdx.x;
    int lane = t & 31, wid = t >> 5;

    float a = p[t], b = p[t + 256];
    float m = fmaxf(a, b);
    #pragma unroll
    for (int o = 16; o; o >>= 1) m = fmaxf(m, __shfl_xor_sync(0xffffffffu, m, o));
    if (lane == 0) shm[wid] = m;
    __syncthreads();
    float m2 = shm[0];
    #pragma unroll
    for (int i = 1; i < 8; i++) m2 = fmaxf(m2, shm[i]);

    float e0 = __expf(a - m2), e1 = __expf(b - m2);
    float s = e0 + e1;
    #pragma unroll
    for (int o = 16; o; o >>= 1) s += __shfl_xor_sync(0xffffffffu, s, o);
    if (lane == 0) shs[wid] = s;
    __syncthreads();
    float s2 = 0.f;
    #pragma unroll
    for (int i = 0; i < 8; i++) s2 += shs[i];
    float inv = 1.f / s2;
    split1(e0 * inv, ph, pl, row * 512 + t);
    split1(e1 * inv, ph, pl, row * 512 + t + 256);
}

__global__ void __launch_bounds__(256) gate4_kernel(
    const float* __restrict__ t0, const float* __restrict__ f1,
    const float* __restrict__ f2, const float* __restrict__ f3,
    float* __restrict__ out)
{
    __shared__ float shm[8];
    __shared__ float shs[8];
    size_t row = blockIdx.x;
    size_t base = row * 768;
    float* q = out + base;
    int t = threadIdx.x;
    int lane = t & 31, wid = t >> 5;

    float a = t0[base + t]       + f1[base + t]       + f2[base + t]       + f3[base + t];
    float b = t0[base + t + 256] + f1[base + t + 256] + f2[base + t + 256] + f3[base + t + 256];
    float c = t0[base + t + 512] + f1[base + t + 512] + f2[base + t + 512] + f3[base + t + 512];
    float m = fmaxf(fmaxf(a, b), c);
    #pragma unroll
    for (int o = 16; o; o >>= 1) m = fmaxf(m, __shfl_xor_sync(0xffffffffu, m, o));
    if (lane == 0) shm[wid] = m;
    __syncthreads();
    float m2 = shm[0];
    #pragma unroll
    for (int i = 1; i < 8; i++) m2 = fmaxf(m2, shm[i]);

    float e0 = __expf(a - m2), e1 = __expf(b - m2), e2 = __expf(c - m2);
    float s = e0 + e1 + e2;
    #pragma unroll
    for (int o = 16; o; o >>= 1) s += __shfl_xor_sync(0xffffffffu, s, o);
    if (lane == 0) shs[wid] = s;
    __syncthreads();
    float s2 = 0.f;
    #pragma unroll
    for (int i = 0; i < 8; i++) s2 += shs[i];
    float inv = 1.f / s2;
    q[t]       = a + a * e0 * inv;
    q[t + 256] = b + b * e1 * inv;
    q[t + 512] = c + c * e2 * inv;
}

__global__ void __launch_bounds__(256) gate_split_kernel(
    const float* __restrict__ in, bf16* __restrict__ oh, bf16* __restrict__ ol)
{
    __shared__ float shm[8];
    __shared__ float shs[8];
    size_t row = blockIdx.x;
    const float* p = in + row * 768;
    int t = threadIdx.x;
    int lane = t & 31, wid = t >> 5;

    float a = p[t], b = p[t + 256], c = p[t + 512];
    float m = fmaxf(fmaxf(a, b), c);
    #pragma unroll
    for (int o = 16; o; o >>= 1) m = fmaxf(m, __shfl_xor_sync(0xffffffffu, m, o));
    if (lane == 0) shm[wid] = m;
    __syncthreads();
    float m2 = shm[0];
    #pragma unroll
    for (int i = 1; i < 8; i++) m2 = fmaxf(m2, shm[i]);

    float e0 = __expf(a - m2), e1 = __expf(b - m2), e2 = __expf(c - m2);
    float s = e0 + e1 + e2;
    #pragma unroll
    for (int o = 16; o; o >>= 1) s += __shfl_xor_sync(0xffffffffu, s, o);
    if (lane == 0) shs[wid] = s;
    __syncthreads();
    float s2 = 0.f;
    #pragma unroll
    for (int i = 0; i < 8; i++) s2 += shs[i];
    float inv = 1.f / s2;
    split1(a + a * e0 * inv, oh, ol, row * 768 + t);
    split1(b + b * e1 * inv, oh, ol, row * 768 + t + 256);
    split1(c + c * e2 * inv, oh, ol, row * 768 + t + 512);
}

// ======================= HMMA core =======================
#define HG_SMEM (3 * 32768)

// B loaded once per tile via ldmatrix.x4 (4 K-chunks per nf); A streamed per mf.
// Per-accumulator order unchanged (ah*bh, ah*bl, al*bh per kc) -> bit-exact.
#define HMMA_COMPUTE(tb)                                                             \
    {                                                                                \
        uint32_t bh[4][4], bl[4][4];                                                 \
        _Pragma("unroll")                                                            \
        for (int nf = 0; nf < 4; nf++) {                                             \
            int r = wn + 8 * nf + (lane & 7);                                        \
            uint32_t co = (uint32_t)(r * 64 + (((lane >> 3) ^ ((r >> 1) & 3)) << 4)); \
            ldmx4(bh[nf][0], bh[nf][1], bh[nf][2], bh[nf][3], (tb) + 16384 + co);    \
            ldmx4(bl[nf][0], bl[nf][1], bl[nf][2], bl[nf][3], (tb) + 24576 + co);    \
        }                                                                            \
        _Pragma("unroll")                                                            \
        for (int kc = 0; kc < 2; kc++) {                                             \
            _Pragma("unroll")                                                        \
            for (int mf = 0; mf < 4; mf++) {                                         \
                int r = wm + 16 * mf + rA;                                           \
                uint32_t ao = (uint32_t)(r * 64 + (((kc * 2 + khA) ^ ((r >> 1) & 3)) << 4)); \
                uint32_t a0, a1, a2, a3;                                             \
                ldmx4(a0, a1, a2, a3, (tb) + ao);                                    \
                _Pragma("unroll")                                                    \
                for (int nf = 0; nf < 4; nf++)                                       \
                    mma16816(acc[mf][nf], a0, a1, a2, a3, bh[nf][2 * kc], bh[nf][2 * kc + 1]); \
                _Pragma("unroll")                                                    \
                for (int nf = 0; nf < 4; nf++)                                       \
                    mma16816(acc[mf][nf], a0, a1, a2, a3, bl[nf][2 * kc], bl[nf][2 * kc + 1]); \
                ldmx4(a0, a1, a2, a3, (tb) + 8192 + ao);                             \
                _Pragma("unroll")                                                    \
                for (int nf = 0; nf < 4; nf++)                                       \
                    mma16816(acc[mf][nf], a0, a1, a2, a3, bh[nf][2 * kc], bh[nf][2 * kc + 1]); \
            }                                                                        \
        }                                                                            \
    }

#define HMMA_MAINLOOP()                                                              \
    loadTile(0, 0); cp_commit();                                                     \
    loadTile(1, 32); cp_commit();                                                    \
    for (int kt = 0; kt < NIT; kt++) {                                               \
        if (kt == NIT - 1) cp_wait<0>(); else cp_wait<1>();                          \
        __syncthreads();                                                             \
        if (kt + 2 < NIT) { loadTile((kt + 2) % 3, (kt + 2) * 32); cp_commit(); }    \
        uint32_t tb = sb + (uint32_t)((kt % 3) * 32768);                             \
        HMMA_COMPUTE(tb)                                                             \
    }

#define HMMA_PROLOGUE()                                                              \
    extern __shared__ char smem[];                                                   \
    uint32_t sb = smem_u32(smem);                                                    \
    const int tid = threadIdx.x;                                                     \
    const int rowStart = blockIdx.y * 128, colStart = blockIdx.x * 128;              \
    const int warp = tid >> 5, lane = tid & 31;                                      \
    const int wm = (warp & 1) * 64, wn = (warp >> 1) * 32;                           \
    const int ldRow = tid >> 1;                                                      \
    const int ldC0 = (tid & 1) * 2;                                                  \
    const uint32_t so0 = swz(ldRow, ldC0);                                           \
    const uint32_t so1 = swz(ldRow, ldC0 + 1);                                       \
    const int rA = lane & 15, khA = lane >> 4;                                       \
    float acc[4][4][4];                                                              \
    _Pragma("unroll")                                                                \
    for (int i = 0; i < 4; i++)                                                      \
        _Pragma("unroll")                                                            \
        for (int j = 0; j < 4; j++)                                                  \
            _Pragma("unroll")                                                        \
            for (int c = 0; c < 4; c++) acc[i][j][c] = 0.f;

#define QKV_EPILOGUE(isV)                                                            \
    {                                                                                \
        const int g = lane >> 2, q4 = lane & 3;                                      \
        const float coef = -0.034603417655075f;                                      \
        _Pragma("unroll")                                                            \
        for (int nf = 0; nf < 4; nf++) {                                             \
            int c = colStart + wn + 8 * nf + 2 * q4;                                 \
            float bx = bias[c], by = bias[c + 1];                                    \
            _Pragma("unroll")                                                        \
            for (int mf = 0; mf < 4; mf++) {                                         \
                int r0 = rowStart + wm + 16 * mf + g;                                \
                float v0 = acc[mf][nf][0] + bx;                                      \
                float v1 = acc[mf][nf][1] + by;                                      \
                float v2 = acc[mf][nf][2] + bx;                                      \
                float v3 = acc[mf][nf][3] + by;                                      \
                if (!(isV)) {                                                        \
                    float theta = exp2f(coef * (float)(c >> 1));                     \
                    int s0 = r0 & (SS - 1);                                          \
                    float sn, cs;                                                    \
                    sincosf((float)s0 * theta, &sn, &cs);                            \
                    float x0 = v0 * cs - v1 * sn, x1 = v1 * cs + v0 * sn;            \
                    sincosf((float)(s0 + 8) * theta, &sn, &cs);                      \
                    float x2 = v2 * cs - v3 * sn, x3 = v3 * cs + v2 * sn;            \
                    store_split2(Oh, Ol, (size_t)r0 * 768 + c, x0, x1);              \
                    store_split2(Oh, Ol, (size_t)(r0 + 8) * 768 + c, x2, x3);        \
                } else {                                                             \
                    int bb = r0 >> 9, s0 = r0 & (SS - 1);                            \
                    split1(v0, Oh, Ol, ((size_t)(bb * 768 + c)) * 512 + s0);         \
                    split1(v1, Oh, Ol, ((size_t)(bb * 768 + c + 1)) * 512 + s0);     \
                    split1(v2, Oh, Ol, ((size_t)(bb * 768 + c)) * 512 + s0 + 8);     \
                    split1(v3, Oh, Ol, ((size_t)(bb * 768 + c + 1)) * 512 + s0 + 8); \
                }                                                                    \
            }                                                                        \
        }                                                                            \
    }

// ======================= projection GEMM =======================
// EPI: 0=fp32+bias ; 5=silu+split ; 6=fp32+bias AND split
template <int EPI, int CAT>
__global__ void __launch_bounds__(256, 2) hmma_gemm_kernel(
    const bf16* __restrict__ A1h, const bf16* __restrict__ A1l,
    const bf16* __restrict__ A2h, const bf16* __restrict__ A2l,
    const bf16* __restrict__ Wh, const bf16* __restrict__ Wl,
    const float* __restrict__ bias, float* __restrict__ C,
    bf16* __restrict__ Oh, bf16* __restrict__ Ol, int K)
{
    HMMA_PROLOGUE()
    const int NIT = K / 32;

    auto loadTile = [&](int buf, int k0) {
        uint32_t base = sb + buf * 32768;
        int kk = k0 + ldC0 * 8;
        const bf16 *ph, *pl; size_t aoff;
        if (!CAT) {
            ph = A1h; pl = A1l; aoff = (size_t)(rowStart + ldRow) * K + kk;
        } else if (k0 < 768) {
            ph = A1h; pl = A1l; aoff = (size_t)(rowStart + ldRow) * 768 + kk;
        } else {
            ph = A2h; pl = A2l; aoff = (size_t)(rowStart + ldRow) * 768 + (kk - 768);
        }
        cp_async16(base + so0, ph + aoff);
        cp_async16(base + so1, ph + aoff + 8);
        cp_async16(base + 8192 + so0, pl + aoff);
        cp_async16(base + 8192 + so1, pl + aoff + 8);
        size_t boff = (size_t)(colStart + ldRow) * K + kk;
        cp_async16(base + 16384 + so0, Wh + boff);
        cp_async16(base + 16384 + so1, Wh + boff + 8);
        cp_async16(base + 24576 + so0, Wl + boff);
        cp_async16(base + 24576 + so1, Wl + boff + 8);
    };

    HMMA_MAINLOOP()

    const int g = lane >> 2, q4 = lane & 3;
    #pragma unroll
    for (int nf = 0; nf < 4; nf++) {
        int c = colStart + wn + 8 * nf + 2 * q4;
        float bx = bias[c], by = bias[c + 1];
        #pragma unroll
        for (int mf = 0; mf < 4; mf++) {
            int r0 = rowStart + wm + 16 * mf + g;
            float v0 = acc[mf][nf][0] + bx;
            float v1 = acc[mf][nf][1] + by;
            float v2 = acc[mf][nf][2] + bx;
            float v3 = acc[mf][nf][3] + by;
            if (EPI == 0 || EPI == 6) {
                *(float2*)(C + (size_t)r0 * 768 + c) = make_float2(v0, v1);
                *(float2*)(C + (size_t)(r0 + 8) * 768 + c) = make_float2(v2, v3);
                if (EPI == 6) {
                    store_split2(Oh, Ol, (size_t)r0 * 768 + c, v0, v1);
                    store_split2(Oh, Ol, (size_t)(r0 + 8) * 768 + c, v2, v3);
                }
            } else { // silu + split
                v0 *= 1.f / (1.f + __expf(-v0));
                v1 *= 1.f / (1.f + __expf(-v1));
                v2 *= 1.f / (1.f + __expf(-v2));
                v3 *= 1.f / (1.f + __expf(-v3));
                store_split2(Oh, Ol, (size_t)r0 * 768 + c, v0, v1);
                store_split2(Oh, Ol, (size_t)(r0 + 8) * 768 + c, v2, v3);
            }
        }
    }
}

// ======================= fused dual-attention QKV =======================
__global__ void __launch_bounds__(256, 2) hmma_qkv2_kernel(
    const bf16* __restrict__ aq0h, const bf16* __restrict__ aq0l,
    const bf16* __restrict__ akv0h, const bf16* __restrict__ akv0l,
    const bf16* __restrict__ aq1h, const bf16* __restrict__ aq1l,
    const bf16* __restrict__ akv1h, const bf16* __restrict__ akv1l,
    const bf16* __restrict__ w0h, const bf16* __restrict__ w0l,
    const bf16* __restrict__ w1h, const bf16* __restrict__ w1l,
    const float* __restrict__ bq0, const float* __restrict__ bk0, const float* __restrict__ bv0,
    const float* __restrict__ bq1, const float* __restrict__ bk1, const float* __restrict__ bv1,
    bf16* __restrict__ q0h, bf16* __restrict__ q0l,
    bf16* __restrict__ k0h, bf16* __restrict__ k0l,
    bf16* __restrict__ vt0h, bf16* __restrict__ vt0l,
    bf16* __restrict__ q1h, bf16* __restrict__ q1l,
    bf16* __restrict__ k1h, bf16* __restrict__ k1l,
    bf16* __restrict__ vt1h, bf16* __restrict__ vt1l)
{
    HMMA_PROLOGUE()
    const int z = blockIdx.z;
    const int att = z / 3, c3 = z - att * 3;
    const bf16* Ah = (c3 == 0) ? (att ? aq1h : aq0h) : (att ? akv1h : akv0h);
    const bf16* Al = (c3 == 0) ? (att ? aq1l : aq0l) : (att ? akv1l : akv0l);
    const bf16* Wh = (att ? w1h : w0h) + (size_t)c3 * WSZ;
    const bf16* Wl = (att ? w1l : w0l) + (size_t)c3 * WSZ;
    const float* bias = att ? (c3 == 0 ? bq1 : c3 == 1 ? bk1 : bv1)
                            : (c3 == 0 ? bq0 : c3 == 1 ? bk0 : bv0);
    bf16* Oh = att ? (c3 == 0 ? q1h : c3 == 1 ? k1h : vt1h)
                   : (c3 == 0 ? q0h : c3 == 1 ? k0h : vt0h);
    bf16* Ol = att ? (c3 == 0 ? q1l : c3 == 1 ? k1l : vt1l)
                   : (c3 == 0 ? q0l : c3 == 1 ? k0l : vt0l);

    const int NIT = 24;
    auto loadTile = [&](int buf, int k0) {
        uint32_t base = sb + buf * 32768;
        int kk = k0 + ldC0 * 8;
        size_t aoff = (size_t)(rowStart + ldRow) * 768 + kk;
        cp_async16(base + so0, Ah + aoff);
        cp_async16(base + so1, Ah + aoff + 8);
        cp_async16(base + 8192 + so0, Al + aoff);
        cp_async16(base + 8192 + so1, Al + aoff + 8);
        size_t boff = (size_t)(colStart + ldRow) * 768 + kk;
        cp_async16(base + 16384 + so0, Wh + boff);
        cp_async16(base + 16384 + so1, Wh + boff + 8);
        cp_async16(base + 24576 + so0, Wl + boff);
        cp_async16(base + 24576 + so1, Wl + boff + 8);
    };
    HMMA_MAINLOOP()
    QKV_EPILOGUE(c3 == 2)
}

// single-attention QKV (stage 3)
__global__ void __launch_bounds__(256, 2) hmma_qkv_kernel(
    const bf16* __restrict__ Aqh, const bf16* __restrict__ Aql,
    const bf16* __restrict__ Akvh, const bf16* __restrict__ Akvl,
    const bf16* __restrict__ Wbh, const bf16* __restrict__ Wbl,
    const float* __restrict__ bq, const float* __restrict__ bk, const float* __restrict__ bv,
    bf16* __restrict__ Qh, bf16* __restrict__ Ql2,
    bf16* __restrict__ Kh, bf16* __restrict__ Kl,
    bf16* __restrict__ Vth, bf16* __restrict__ Vtl)
{
    HMMA_PROLOGUE()
    const int z = blockIdx.z;
    const bf16* Ah = (z == 0) ? Aqh : Akvh;
    const bf16* Al = (z == 0) ? Aql : Akvl;
    const bf16* Wh = Wbh + (size_t)z * WSZ;
    const bf16* Wl = Wbl + (size_t)z * WSZ;
    const float* bias = (z == 0) ? bq : (z == 1) ? bk : bv;
    bf16* Oh = (z == 0) ? Qh : (z == 1) ? Kh : Vth;
    bf16* Ol = (z == 0) ? Ql2 : (z == 1) ? Kl : Vtl;

    const int NIT = 24;
    auto loadTile = [&](int buf, int k0) {
        uint32_t base = sb + buf * 32768;
        int kk = k0 + ldC0 * 8;
        size_t aoff = (size_t)(rowStart + ldRow) * 768 + kk;
        cp_async16(base + so0, Ah + aoff);
        cp_async16(base + so1, Ah + aoff + 8);
        cp_async16(base + 8192 + so0, Al + aoff);
        cp_async16(base + 8192 + so1, Al + aoff + 8);
        size_t boff = (size_t)(colStart + ldRow) * 768 + kk;
        cp_async16(base + 16384 + so0, Wh + boff);
        cp_async16(base + 16384 + so1, Wh + boff + 8);
        cp_async16(base + 24576 + so0, Wl + boff);
        cp_async16(base + 24576 + so1, Wl + boff + 8);
    };
    HMMA_MAINLOOP()
    QKV_EPILOGUE(z == 2)
}

// ======================= fused dual score =======================
__global__ void __launch_bounds__(256, 2) hmma_score2_kernel(
    const bf16* __restrict__ q0h, const bf16* __restrict__ q0l,
    const bf16* __restrict__ k0h, const bf16* __restrict__ k0l,
    const bf16* __restrict__ q1h, const bf16* __restrict__ q1l,
    const bf16* __restrict__ k1h, const bf16* __restrict__ k1l,
    float* __restrict__ Sc)
{
    HMMA_PROLOGUE()
    const int z = blockIdx.z;
    const int att = z >> 5, b = z & 31;
    const bf16* Qh = att ? q1h : q0h;
    const bf16* Ql = att ? q1l : q0l;
    const bf16* Kh = att ? k1h : k0h;
    const bf16* Kl = att ? k1l : k0l;

    const int NIT = 24;
    auto loadTile = [&](int buf, int k0) {
        uint32_t base = sb + buf * 32768;
        int kk = k0 + ldC0 * 8;
        size_t aoff = (size_t)(b * 512 + rowStart + ldRow) * 768 + kk;
        size_t boff = (size_t)(b * 512 + colStart + ldRow) * 768 + kk;
        cp_async16(base + so0, Qh + aoff);
        cp_async16(base + so1, Qh + aoff + 8);
        cp_async16(base + 8192 + so0, Ql + aoff);
        cp_async16(base + 8192 + so1, Ql + aoff + 8);
        cp_async16(base + 16384 + so0, Kh + boff);
        cp_async16(base + 16384 + so1, Kh + boff + 8);
        cp_async16(base + 24576 + so0, Kl + boff);
        cp_async16(base + 24576 + so1, Kl + boff + 8);
    };
    HMMA_MAINLOOP()

    float* C = Sc + (size_t)z * 262144;
    const int g = lane >> 2, q4 = lane & 3;
    #pragma unroll
    for (int nf = 0; nf < 4; nf++) {
        int c = colStart + wn + 8 * nf + 2 * q4;
        #pragma unroll
        for (int mf = 0; mf < 4; mf++) {
            int r0 = rowStart + wm + 16 * mf + g;
            *(float2*)(C + (size_t)r0 * 512 + c) =
                make_float2(8.f * acc[mf][nf][0], 8.f * acc[mf][nf][1]);
            *(float2*)(C + (size_t)(r0 + 8) * 512 + c) =
                make_float2(8.f * acc[mf][nf][2], 8.f * acc[mf][nf][3]);
        }
    }
}

// single-attention score (stage 3, H heads)
__global__ void __launch_bounds__(256, 2) hmma_score_kernel(
    const bf16* __restrict__ Qh, const bf16* __restrict__ Ql,
    const bf16* __restrict__ Kh, const bf16* __restrict__ Kl,
    float* __restrict__ Sc, int H, int hd)
{
    HMMA_PROLOGUE()
    const int z = blockIdx.z, b = z / H, h = z - b * H;
    const int NIT = hd / 32;
    auto loadTile = [&](int buf, int k0) {
        uint32_t base = sb + buf * 32768;
        int kk = k0 + ldC0 * 8;
        size_t aoff = (size_t)(b * 512 + rowStart + ldRow) * 768 + h * hd + kk;
        size_t boff = (size_t)(b * 512 + colStart + ldRow) * 768 + h * hd + kk;
        cp_async16(base + so0, Qh + aoff);
        cp_async16(base + so1, Qh + aoff + 8);
        cp_async16(base + 8192 + so0, Ql + aoff);
        cp_async16(base + 8192 + so1, Ql + aoff + 8);
        cp_async16(base + 16384 + so0, Kh + boff);
        cp_async16(base + 16384 + so1, Kh + boff + 8);
        cp_async16(base + 24576 + so0, Kl + boff);
        cp_async16(base + 24576 + so1, Kl + boff + 8);
    };
    HMMA_MAINLOOP()

    float* C = Sc + (size_t)z * 262144;
    const int g = lane >> 2, q4 = lane & 3;
    #pragma unroll
    for (int nf = 0; nf < 4; nf++) {
        int c = colStart + wn + 8 * nf + 2 * q4;
        #pragma unroll
        for (int mf = 0; mf < 4; mf++) {
            int r0 = rowStart + wm + 16 * mf + g;
            *(float2*)(C + (size_t)r0 * 512 + c) =
                make_float2(8.f * acc[mf][nf][0], 8.f * acc[mf][nf][1]);
            *(float2*)(C + (size_t)(r0 + 8) * 512 + c) =
                make_float2(8.f * acc[mf][nf][2], 8.f * acc[mf][nf][3]);
        }
    }
}

// ======================= fused dual PV =======================
__global__ void __launch_bounds__(256, 2) hmma_pv2_kernel(
    const bf16* __restrict__ Ph, const bf16* __restrict__ Pl,
    const bf16* __restrict__ vt0h, const bf16* __restrict__ vt0l,
    const bf16* __restrict__ vt1h, const bf16* __restrict__ vt1l,
    bf16* __restrict__ o0h, bf16* __restrict__ o0l,
    bf16* __restrict__ o1h, bf16* __restrict__ o1l)
{
    HMMA_PROLOGUE()
    const int z = blockIdx.z;
    const int att = z >> 5, b = z & 31;
    const bf16* Vth = att ? vt1h : vt0h;
    const bf16* Vtl = att ? vt1l : vt0l;
    bf16* Oh = att ? o1h : o0h;
    bf16* Ol = att ? o1l : o0l;

    const int NIT = 16;
    auto loadTile = [&](int buf, int k0) {
        uint32_t base = sb + buf * 32768;
        int kk = k0 + ldC0 * 8;
        size_t aoff = (size_t)z * 262144 + (size_t)(rowStart + ldRow) * 512 + kk;
        size_t boff = (size_t)(b * 768 + colStart + ldRow) * 512 + kk;
        cp_async16(base + so0, Ph + aoff);
        cp_async16(base + so1, Ph + aoff + 8);
        cp_async16(base + 8192 + so0, Pl + aoff);
        cp_async16(base + 8192 + so1, Pl + aoff + 8);
        cp_async16(base + 16384 + so0, Vth + boff);
        cp_async16(base + 16384 + so1, Vth + boff + 8);
        cp_async16(base + 24576 + so0, Vtl + boff);
        cp_async16(base + 24576 + so1, Vtl + boff + 8);
    };
    HMMA_MAINLOOP()

    const int g = lane >> 2, q4 = lane & 3;
    #pragma unroll
    for (int nf = 0; nf < 4; nf++) {
        int c = colStart + wn + 8 * nf + 2 * q4;
        #pragma unroll
        for (int mf = 0; mf < 4; mf++) {
            int r0 = b * 512 + rowStart + wm + 16 * mf + g;
            store_split2(Oh, Ol, (size_t)r0 * 768 + c, acc[mf][nf][0], acc[mf][nf][1]);
            store_split2(Oh, Ol, (size_t)(r0 + 8) * 768 + c, acc[mf][nf][2], acc[mf][nf][3]);
        }
    }
}

// single-attention PV (stage 3)
__global__ void __launch_bounds__(256, 2) hmma_pv_kernel(
    const bf16* __restrict__ Ph, const bf16* __restrict__ Pl,
    const bf16* __restrict__ Vth, const bf16* __restrict__ Vtl,
    bf16* __restrict__ Oh, bf16* __restrict__ Ol, int H, int hd)
{
    HMMA_PROLOGUE()
    const int z = blockIdx.z, b = z / H, h = z - b * H;
    const int NIT = 16;
    auto loadTile = [&](int buf, int k0) {
        uint32_t base = sb + buf * 32768;
        int kk = k0 + ldC0 * 8;
        size_t aoff = (size_t)z * 262144 + (size_t)(rowStart + ldRow) * 512 + kk;
        size_t boff = (size_t)(b * 768 + h * hd + colStart + ldRow) * 512 + kk;
        cp_async16(base + so0, Ph + aoff);
        cp_async16(base + so1, Ph + aoff + 8);
        cp_async16(base + 8192 + so0, Pl + aoff);
        cp_async16(base + 8192 + so1, Pl + aoff + 8);
        cp_async16(base + 16384 + so0, Vth + boff);
        cp_async16(base + 16384 + so1, Vth + boff + 8);
        cp_async16(base + 24576 + so0, Vtl + boff);
        cp_async16(base + 24576 + so1, Vtl + boff + 8);
    };
    HMMA_MAINLOOP()

    const int g = lane >> 2, q4 = lane & 3;
    #pragma unroll
    for (int nf = 0; nf < 4; nf++) {
        int cl = colStart + wn + 8 * nf + 2 * q4;
        if (cl < hd) {
            int c = h * hd + cl;
            #pragma unroll
            for (int mf = 0; mf < 4; mf++) {
                int r0 = b * 512 + rowStart + wm + 16 * mf + g;
                store_split2(Oh, Ol, (size_t)r0 * 768 + c, acc[mf][nf][0], acc[mf][nf][1]);
                store_split2(Oh, Ol, (size_t)(r0 + 8) * 768 + c, acc[mf][nf][2], acc[mf][nf][3]);
            }
        }
    }
}

// ======================= host =======================
extern "C" void kernel_launch(void* const* d_in, const int* in_sizes, int n_in,
                              void* d_out, int out_size)
{
    (void)n_in; (void)out_size;
    const float *text, *vtab, *atab;
    const float *aw[18];
    const float *fcw, *fcb, *f1w, *f1b, *f2w, *f2b, *catw, *catb;
    const int *vid, *aid;

    if (in_sizes[1] == MR) {
        text = (const float*)d_in[0];
        vid  = (const int*)d_in[1];
        aid  = (const int*)d_in[2];
        vtab = (const float*)d_in[3];
        atab = (const float*)d_in[4];
        for (int i = 0; i < 18; i++) aw[i] = (const float*)d_in[5 + i];
        fcw = (const float*)d_in[23]; fcb = (const float*)d_in[24];
        f1w = (const float*)d_in[25]; f1b = (const float*)d_in[26];
        f2w = (const float*)d_in[27]; f2b = (const float*)d_in[28];
        catw = (const float*)d_in[29]; catb = (const float*)d_in[30];
    } else {
        text = (const float*)d_in[0];
        vtab = (const float*)d_in[1];
        atab = (const float*)d_in[2];
        for (int i = 0; i < 18; i++) aw[i] = (const float*)d_in[3 + i];
        fcw = (const float*)d_in[21]; fcb = (const float*)d_in[22];
        f1w = (const float*)d_in[23]; f1b = (const float*)d_in[24];
        f2w = (const float*)d_in[25]; f2b = (const float*)d_in[26];
        catw = (const float*)d_in[27]; catb = (const float*)d_in[28];
        vid  = (const int*)d_in[29];
        aid  = (const int*)d_in[30];
    }

    cudaFuncSetAttribute(hmma_gemm_kernel<0,0>, cudaFuncAttributeMaxDynamicSharedMemorySize, HG_SMEM);
    cudaFuncSetAttribute(hmma_gemm_kernel<5,0>, cudaFuncAttributeMaxDynamicSharedMemorySize, HG_SMEM);
    cudaFuncSetAttribute(hmma_gemm_kernel<6,0>, cudaFuncAttributeMaxDynamicSharedMemorySize, HG_SMEM);
    cudaFuncSetAttribute(hmma_gemm_kernel<0,1>, cudaFuncAttributeMaxDynamicSharedMemorySize, HG_SMEM);
    cudaFuncSetAttribute(hmma_qkv_kernel, cudaFuncAttributeMaxDynamicSharedMemorySize, HG_SMEM);
    cudaFuncSetAttribute(hmma_qkv2_kernel, cudaFuncAttributeMaxDynamicSharedMemorySize, HG_SMEM);
    cudaFuncSetAttribute(hmma_score_kernel, cudaFuncAttributeMaxDynamicSharedMemorySize, HG_SMEM);
    cudaFuncSetAttribute(hmma_score2_kernel, cudaFuncAttributeMaxDynamicSharedMemorySize, HG_SMEM);
    cudaFuncSetAttribute(hmma_pv_kernel, cudaFuncAttributeMaxDynamicSharedMemorySize, HG_SMEM);
    cudaFuncSetAttribute(hmma_pv2_kernel, cudaFuncAttributeMaxDynamicSharedMemorySize, HG_SMEM);

    float *sc, *F1, *F2, *F3;
    bf16 *wth, *wtl, *cth, *ctl;
    bf16 *spt_h, *spt_l, *sev_h, *sev_l, *sea_h, *sea_l;
    bf16 *sq_h, *sq_l, *sk_h, *sk_l, *svt_h, *svt_l;
    bf16 *sq2_h, *sq2_l, *sk2_h, *sk2_l, *svt2_h, *svt2_l;
    bf16 *sp_h, *sp_l;
    bf16 *s1_h, *s1_l, *s2_h, *s2_l, *s3_h, *s3_l, *s4_h, *s4_l;
    bf16 *c1_h, *c1_l, *c2_h, *c2_l, *c3_h, *c3_l;
    cudaGetSymbolAddress((void**)&sc, g_sc);
    cudaGetSymbolAddress((void**)&F1, g_F1);
    cudaGetSymbolAddress((void**)&F2, g_F2);
    cudaGetSymbolAddress((void**)&F3, g_F3);
    cudaGetSymbolAddress((void**)&wth, g_wth);
    cudaGetSymbolAddress((void**)&wtl, g_wtl);
    cudaGetSymbolAddress((void**)&cth, g_cth);
    cudaGetSymbolAddress((void**)&ctl, g_ctl);
    cudaGetSymbolAddress((void**)&spt_h, g_spt_h); cudaGetSymbolAddress((void**)&spt_l, g_spt_l);
    cudaGetSymbolAddress((void**)&sev_h, g_sev_h); cudaGetSymbolAddress((void**)&sev_l, g_sev_l);
    cudaGetSymbolAddress((void**)&sea_h, g_sea_h); cudaGetSymbolAddress((void**)&sea_l, g_sea_l);
    cudaGetSymbolAddress((void**)&sq_h, g_sq_h);   cudaGetSymbolAddress((void**)&sq_l, g_sq_l);
    cudaGetSymbolAddress((void**)&sk_h, g_sk_h);   cudaGetSymbolAddress((void**)&sk_l, g_sk_l);
    cudaGetSymbolAddress((void**)&svt_h, g_svt_h); cudaGetSymbolAddress((void**)&svt_l, g_svt_l);
    cudaGetSymbolAddress((void**)&sq2_h, g_sq2_h); cudaGetSymbolAddress((void**)&sq2_l, g_sq2_l);
    cudaGetSymbolAddress((void**)&sk2_h, g_sk2_h); cudaGetSymbolAddress((void**)&sk2_l, g_sk2_l);
    cudaGetSymbolAddress((void**)&svt2_h, g_svt2_h); cudaGetSymbolAddress((void**)&svt2_l, g_svt2_l);
    cudaGetSymbolAddress((void**)&sp_h, g_sp_h);   cudaGetSymbolAddress((void**)&sp_l, g_sp_l);
    cudaGetSymbolAddress((void**)&s1_h, g_s1_h);   cudaGetSymbolAddress((void**)&s1_l, g_s1_l);
    cudaGetSymbolAddress((void**)&s2_h, g_s2_h);   cudaGetSymbolAddress((void**)&s2_l, g_s2_l);
    cudaGetSymbolAddress((void**)&s3_h, g_s3_h);   cudaGetSymbolAddress((void**)&s3_l, g_s3_l);
    cudaGetSymbolAddress((void**)&s4_h, g_s4_h);   cudaGetSymbolAddress((void**)&s4_l, g_s4_l);
    cudaGetSymbolAddress((void**)&c1_h, g_c1_h);   cudaGetSymbolAddress((void**)&c1_l, g_c1_l);
    cudaGetSymbolAddress((void**)&c2_h, g_c2_h);   cudaGetSymbolAddress((void**)&c2_l, g_c2_l);
    cudaGetSymbolAddress((void**)&c3_h, g_c3_h);   cudaGetSymbolAddress((void**)&c3_l, g_c3_l);

    const int EW = (NEL + 255) / 256;
    const dim3 gHG(6, 128);

    // -------- weight prep --------
    wsplit12_kernel<<<dim3(24, 24, 12), 256>>>(
        aw[0], aw[2], aw[4], aw[6], aw[8], aw[10],
        aw[12], aw[14], aw[16], fcw, f1w, f2w, wth, wtl);
    wsplit_kernel<<<dim3(48, 24), 256>>>(catw, cth, ctl, 1536);

    auto GEMM_F = [&](const bf16* Ah, const bf16* Al, int wi, const float* bi, float* Cc) {
        hmma_gemm_kernel<0,0><<<gHG, 256, HG_SMEM>>>(Ah, Al, nullptr, nullptr,
            wth + (size_t)wi * WSZ, wtl + (size_t)wi * WSZ, bi, Cc, nullptr, nullptr, 768);
    };
    auto GEMM_FS = [&](const bf16* Ah, const bf16* Al, int wi, const float* bi, float* Cc,
                       bf16* oh, bf16* ol) {
        hmma_gemm_kernel<6,0><<<gHG, 256, HG_SMEM>>>(Ah, Al, nullptr, nullptr,
            wth + (size_t)wi * WSZ, wtl + (size_t)wi * WSZ, bi, Cc, oh, ol, 768);
    };
    auto GEMM_SILU = [&](const bf16* Ah, const bf16* Al, int wi, const float* bi, bf16* oh, bf16* ol) {
        hmma_gemm_kernel<5,0><<<gHG, 256, HG_SMEM>>>(Ah, Al, nullptr, nullptr,
            wth + (size_t)wi * WSZ, wtl + (size_t)wi * WSZ, bi, nullptr, oh, ol, 768);
    };
    auto CATGEMM = [&](const bf16* A1h, const bf16* A1l, const bf16* A2h, const bf16* A2l,
                       const float* bi, float* Cc) {
        hmma_gemm_kernel<0,1><<<gHG, 256, HG_SMEM>>>(A1h, A1l, A2h, A2l, cth, ctl, bi, Cc,
                                                     nullptr, nullptr, 1536);
    };
    auto ATT2 = [&](const bf16* q0h_, const bf16* q0l_, const bf16* kv0h_, const bf16* kv0l_,
                    const bf16* q1h_, const bf16* q1l_, const bf16* kv1h_, const bf16* kv1l_,
                    bf16* o0h, bf16* o0l, bf16* o1h, bf16* o1l) {
        hmma_qkv2_kernel<<<dim3(6, 128, 6), 256, HG_SMEM>>>(
            q0h_, q0l_, kv0h_, kv0l_, q1h_, q1l_, kv1h_, kv1l_,
            wth, wtl, wth + 3 * (size_t)WSZ, wtl + 3 * (size_t)WSZ,
            aw[1], aw[3], aw[5], aw[7], aw[9], aw[11],
            sq_h, sq_l, sk_h, sk_l, svt_h, svt_l,
            sq2_h, sq2_l, sk2_h, sk2_l, svt2_h, svt2_l);
        hmma_score2_kernel<<<dim3(4, 4, 64), 256, HG_SMEM>>>(
            sq_h, sq_l, sk_h, sk_l, sq2_h, sq2_l, sk2_h, sk2_l, sc);
        softmax_split_kernel<<<2 * MR, 256>>>(sc, sp_h, sp_l);
        hmma_pv2_kernel<<<dim3(6, 4, 64), 256, HG_SMEM>>>(
            sp_h, sp_l, svt_h, svt_l, svt2_h, svt2_l, o0h, o0l, o1h, o1l);
    };
    auto FFN = [&](float* x) {   // scratch: c1, c2 only
        gate_split_kernel<<<MR, 256>>>(x, c1_h, c1_l);
        GEMM_SILU(c1_h, c1_l, 10, f1b, c2_h, c2_l);
        GEMM_F(c2_h, c2_l, 11, f2b, x);
    };

    // -------- forward --------
    prep3_kernel<<<dim3(EW, 3), 256>>>(text, vtab, atab, vid, aid,
                                       spt_h, spt_l, sev_h, sev_l, sea_h, sea_l);

    // stage 1: visual_=hv(text,emb_v), acoustic_=ha(text,emb_a)
    ATT2(spt_h, spt_l, sev_h, sev_l, spt_h, spt_l, sea_h, sea_l, s1_h, s1_l, s2_h, s2_l);
    CATGEMM(s1_h, s1_l, s2_h, s2_l, catb, F1);
    // FFN(F1) with fused split of final output into DEDICATED c3 (survives stage 2)
    gate_split_kernel<<<MR, 256>>>(F1, c1_h, c1_l);
    GEMM_SILU(c1_h, c1_l, 10, f1b, c2_h, c2_l);
    GEMM_FS(c2_h, c2_l, 11, f2b, F1, c3_h, c3_l);   // F1 fp32 + split -> c3

    // stage 2: v=hv(visual_,acoustic_), a=ha(acoustic_,visual_)
    ATT2(s1_h, s1_l, s2_h, s2_l, s2_h, s2_l, s1_h, s1_l, s3_h, s3_l, s4_h, s4_l);
    CATGEMM(s3_h, s3_l, s4_h, s4_l, catb, F2);
    FFN(F2);   // uses c1/c2 — c3 untouched

    // stage 3: F3 = mh8(F1, text) @ fcw + fcb, then FFN   (c3 = split(F1))
    hmma_qkv_kernel<<<dim3(6, 128, 3), 256, HG_SMEM>>>(
        c3_h, c3_l, spt_h, spt_l,
        wth + 6 * (size_t)WSZ, wtl + 6 * (size_t)WSZ,
        aw[13], aw[15], aw[17], sq_h, sq_l, sk_h, sk_l, svt_h, svt_l);
    hmma_score_kernel<<<dim3(4, 4, 256), 256, HG_SMEM>>>(sq_h, sq_l, sk_h, sk_l, sc, 8, 96);
    softmax_split_kernel<<<BB * 8 * SS, 256>>>(sc, sp_h, sp_l);
    hmma_pv_kernel<<<dim3(1, 4, 256), 256, HG_SMEM>>>(sp_h, sp_l, svt_h, svt_l, c2_h, c2_l, 8, 96);
    GEMM_F(c2_h, c2_l, 9, fcb, F3);
    FFN(F3);

    // out = gate(text + F1 + F2 + F3)
    gate4_kernel<<<MR, 256>>>(text, F1, F2, F3, (float*)d_out);
}

// round 16
// speedup vs baseline: 1.0489x; 1.0489x over previous
#include <cuda_runtime.h>
#include <cuda_bf16.h>
#include <math.h>
#include <stdint.h>

#define DM 768
#define BB 32
#define SS 512
#define MR (BB*SS)          // 16384 rows
#define NEL (MR*DM)         // 12582912

typedef __nv_bfloat16 bf16;

// ======================= helpers =======================
__device__ __forceinline__ uint32_t smem_u32(const void* p) {
    uint32_t a;
    asm("{ .reg .u64 t; cvta.to.shared.u64 t, %1; cvt.u32.u64 %0, t; }" : "=r"(a) : "l"(p));
    return a;
}
__device__ __forceinline__ void cp_async16(uint32_t dst, const void* src) {
    asm volatile("cp.async.cg.shared.global [%0],[%1],16;" :: "r"(dst), "l"(src));
}
__device__ __forceinline__ void cp_commit() { asm volatile("cp.async.commit_group;"); }
template <int N>
__device__ __forceinline__ void cp_wait() { asm volatile("cp.async.wait_group %0;" :: "n"(N)); }
__device__ __forceinline__ void ldmx4(uint32_t& a0, uint32_t& a1, uint32_t& a2, uint32_t& a3, uint32_t addr) {
    asm volatile("ldmatrix.sync.aligned.m8n8.x4.shared.b16 {%0,%1,%2,%3},[%4];"
                 : "=r"(a0), "=r"(a1), "=r"(a2), "=r"(a3) : "r"(addr));
}
__device__ __forceinline__ void ldmx2(uint32_t& b0, uint32_t& b1, uint32_t addr) {
    asm volatile("ldmatrix.sync.aligned.m8n8.x2.shared.b16 {%0,%1},[%2];"
                 : "=r"(b0), "=r"(b1) : "r"(addr));
}
__device__ __forceinline__ void mma16816(float* c, uint32_t a0, uint32_t a1, uint32_t a2, uint32_t a3,
                                         uint32_t b0, uint32_t b1) {
    asm volatile("mma.sync.aligned.m16n8k16.row.col.f32.bf16.bf16.f32 "
                 "{%0,%1,%2,%3},{%4,%5,%6,%7},{%8,%9},{%0,%1,%2,%3};"
                 : "+f"(c[0]), "+f"(c[1]), "+f"(c[2]), "+f"(c[3])
                 : "r"(a0), "r"(a1), "r"(a2), "r"(a3), "r"(b0), "r"(b1));
}
__device__ __forceinline__ uint32_t swz(int row, int chunk) {
    return (uint32_t)(row * 64 + ((chunk ^ ((row >> 1) & 3)) << 4));
}
__device__ __forceinline__ void store_split2(bf16* Oh, bf16* Ol, size_t idx, float a, float b) {
    bf16 ha = __float2bfloat16(a);
    bf16 hb = __float2bfloat16(b);
    __nv_bfloat162 hh; hh.x = ha; hh.y = hb;
    __nv_bfloat162 ll;
    ll.x = __float2bfloat16(a - __bfloat162float(ha));
    ll.y = __float2bfloat16(b - __bfloat162float(hb));
    *(__nv_bfloat162*)(Oh + idx) = hh;
    *(__nv_bfloat162*)(Ol + idx) = ll;
}
__device__ __forceinline__ void split1(float x, bf16* h, bf16* l, size_t idx) {
    bf16 hh = __float2bfloat16(x);
    h[idx] = hh;
    l[idx] = __float2bfloat16(x - __bfloat162float(hh));
}

// ======================= scratch =======================
static __device__ float g_sc[67108864];
static __device__ float g_F1[NEL];
static __device__ float g_F2[NEL];
static __device__ float g_F3[NEL];

#define WSZ (768*768)
static __device__ bf16 g_wth[12 * WSZ];
static __device__ bf16 g_wtl[12 * WSZ];
static __device__ bf16 g_cth[768 * 1536];
static __device__ bf16 g_ctl[768 * 1536];

static __device__ bf16 g_spt_h[NEL], g_spt_l[NEL];
static __device__ bf16 g_sev_h[NEL], g_sev_l[NEL];
static __device__ bf16 g_sea_h[NEL], g_sea_l[NEL];
static __device__ bf16 g_sq_h[NEL],  g_sq_l[NEL];
static __device__ bf16 g_sk_h[NEL],  g_sk_l[NEL];
static __device__ bf16 g_svt_h[NEL + 65536], g_svt_l[NEL + 65536];
static __device__ bf16 g_sq2_h[NEL],  g_sq2_l[NEL];
static __device__ bf16 g_sk2_h[NEL],  g_sk2_l[NEL];
static __device__ bf16 g_svt2_h[NEL + 65536], g_svt2_l[NEL + 65536];
static __device__ bf16 g_sp_h[67108864], g_sp_l[67108864];
static __device__ bf16 g_s1_h[NEL], g_s1_l[NEL];
static __device__ bf16 g_s2_h[NEL], g_s2_l[NEL];
static __device__ bf16 g_s3_h[NEL], g_s3_l[NEL];
static __device__ bf16 g_s4_h[NEL], g_s4_l[NEL];
static __device__ bf16 g_c1_h[NEL], g_c1_l[NEL];
static __device__ bf16 g_c2_h[NEL], g_c2_l[NEL];
static __device__ bf16 g_c3_h[NEL], g_c3_l[NEL];   // dedicated: split(F1), survives stage 2

// ======================= elementwise =======================
__global__ void __launch_bounds__(256) asplit_kernel(
    const float* __restrict__ x, bf16* __restrict__ h, bf16* __restrict__ l)
{
    int i = blockIdx.x * 256 + threadIdx.x;
    if (i >= NEL / 2) return;
    float2 v = ((const float2*)x)[i];
    store_split2(h, l, (size_t)i * 2, v.x, v.y);
}

__global__ void __launch_bounds__(256) embed_split_kernel(
    const float* __restrict__ tab, const int* __restrict__ ids,
    bf16* __restrict__ oh, bf16* __restrict__ ol)
{
    int i = blockIdx.x * 256 + threadIdx.x;
    if (i >= NEL) return;
    int row = i / DM;
    int d = i - row * DM;
    split1(tab[(size_t)ids[row] * DM + d], oh, ol, i);
}

__global__ void __launch_bounds__(256) wsplit_kernel(
    const float* __restrict__ W, bf16* __restrict__ Th, bf16* __restrict__ Tl, int K)
{
    __shared__ float t[32][33];
    int k0 = blockIdx.x * 32, n0 = blockIdx.y * 32;
    int tx = threadIdx.x & 31, ty = threadIdx.x >> 5;
    #pragma unroll
    for (int i = 0; i < 32; i += 8)
        t[ty + i][tx] = W[(size_t)(k0 + ty + i) * 768 + n0 + tx];
    __syncthreads();
    #pragma unroll
    for (int i = 0; i < 32; i += 8)
        split1(t[tx][ty + i], Th, Tl, (size_t)(n0 + ty + i) * K + k0 + tx);
}

__global__ void __launch_bounds__(256) softmax_split_kernel(
    const float* __restrict__ x, bf16* __restrict__ ph, bf16* __restrict__ pl)
{
    __shared__ float shm[8];
    __shared__ float shs[8];
    size_t row = blockIdx.x;
    const float* p = x + row * 512;
    int t = threadIdx.x;
    int lane = t & 31, wid = t >> 5;

    float a = p[t], b = p[t + 256];
    float m = fmaxf(a, b);
    #pragma unroll
    for (int o = 16; o; o >>= 1) m = fmaxf(m, __shfl_xor_sync(0xffffffffu, m, o));
    if (lane == 0) shm[wid] = m;
    __syncthreads();
    float m2 = shm[0];
    #pragma unroll
    for (int i = 1; i < 8; i++) m2 = fmaxf(m2, shm[i]);

    float e0 = __expf(a - m2), e1 = __expf(b - m2);
    float s = e0 + e1;
    #pragma unroll
    for (int o = 16; o; o >>= 1) s += __shfl_xor_sync(0xffffffffu, s, o);
    if (lane == 0) shs[wid] = s;
    __syncthreads();
    float s2 = 0.f;
    #pragma unroll
    for (int i = 0; i < 8; i++) s2 += shs[i];
    float inv = 1.f / s2;
    split1(e0 * inv, ph, pl, row * 512 + t);
    split1(e1 * inv, ph, pl, row * 512 + t + 256);
}

__global__ void __launch_bounds__(256) gate4_kernel(
    const float* __restrict__ t0, const float* __restrict__ f1,
    const float* __restrict__ f2, const float* __restrict__ f3,
    float* __restrict__ out)
{
    __shared__ float shm[8];
    __shared__ float shs[8];
    size_t row = blockIdx.x;
    size_t base = row * 768;
    float* q = out + base;
    int t = threadIdx.x;
    int lane = t & 31, wid = t >> 5;

    float a = t0[base + t]       + f1[base + t]       + f2[base + t]       + f3[base + t];
    float b = t0[base + t + 256] + f1[base + t + 256] + f2[base + t + 256] + f3[base + t + 256];
    float c = t0[base + t + 512] + f1[base + t + 512] + f2[base + t + 512] + f3[base + t + 512];
    float m = fmaxf(fmaxf(a, b), c);
    #pragma unroll
    for (int o = 16; o; o >>= 1) m = fmaxf(m, __shfl_xor_sync(0xffffffffu, m, o));
    if (lane == 0) shm[wid] = m;
    __syncthreads();
    float m2 = shm[0];
    #pragma unroll
    for (int i = 1; i < 8; i++) m2 = fmaxf(m2, shm[i]);

    float e0 = __expf(a - m2), e1 = __expf(b - m2), e2 = __expf(c - m2);
    float s = e0 + e1 + e2;
    #pragma unroll
    for (int o = 16; o; o >>= 1) s += __shfl_xor_sync(0xffffffffu, s, o);
    if (lane == 0) shs[wid] = s;
    __syncthreads();
    float s2 = 0.f;
    #pragma unroll
    for (int i = 0; i < 8; i++) s2 += shs[i];
    float inv = 1.f / s2;
    q[t]       = a + a * e0 * inv;
    q[t + 256] = b + b * e1 * inv;
    q[t + 512] = c + c * e2 * inv;
}

__global__ void __launch_bounds__(256) gate_split_kernel(
    const float* __restrict__ in, bf16* __restrict__ oh, bf16* __restrict__ ol)
{
    __shared__ float shm[8];
    __shared__ float shs[8];
    size_t row = blockIdx.x;
    const float* p = in + row * 768;
    int t = threadIdx.x;
    int lane = t & 31, wid = t >> 5;

    float a = p[t], b = p[t + 256], c = p[t + 512];
    float m = fmaxf(fmaxf(a, b), c);
    #pragma unroll
    for (int o = 16; o; o >>= 1) m = fmaxf(m, __shfl_xor_sync(0xffffffffu, m, o));
    if (lane == 0) shm[wid] = m;
    __syncthreads();
    float m2 = shm[0];
    #pragma unroll
    for (int i = 1; i < 8; i++) m2 = fmaxf(m2, shm[i]);

    float e0 = __expf(a - m2), e1 = __expf(b - m2), e2 = __expf(c - m2);
    float s = e0 + e1 + e2;
    #pragma unroll
    for (int o = 16; o; o >>= 1) s += __shfl_xor_sync(0xffffffffu, s, o);
    if (lane == 0) shs[wid] = s;
    __syncthreads();
    float s2 = 0.f;
    #pragma unroll
    for (int i = 0; i < 8; i++) s2 += shs[i];
    float inv = 1.f / s2;
    split1(a + a * e0 * inv, oh, ol, row * 768 + t);
    split1(b + b * e1 * inv, oh, ol, row * 768 + t + 256);
    split1(c + c * e2 * inv, oh, ol, row * 768 + t + 512);
}

// ======================= HMMA core (R7/R13 proven structure) =======================
#define HG_SMEM (3 * 32768)

#define HMMA_COMPUTE(tb)                                                             \
    _Pragma("unroll")                                                                \
    for (int kc = 0; kc < 2; kc++) {                                                 \
        uint32_t bh0[4], bh1[4], bl0[4], bl1[4];                                     \
        _Pragma("unroll")                                                            \
        for (int nf = 0; nf < 4; nf++) {                                             \
            int r = wn + 8 * nf + rB;                                                \
            uint32_t co = (uint32_t)(r * 64 + (((kc * 2 + khB) ^ ((r >> 1) & 3)) << 4)); \
            ldmx2(bh0[nf], bh1[nf], (tb) + 16384 + co);                              \
            ldmx2(bl0[nf], bl1[nf], (tb) + 24576 + co);                              \
        }                                                                            \
        _Pragma("unroll")                                                            \
        for (int mf = 0; mf < 4; mf++) {                                             \
            int r = wm + 16 * mf + rA;                                               \
            uint32_t ao = (uint32_t)(r * 64 + (((kc * 2 + khA) ^ ((r >> 1) & 3)) << 4)); \
            uint32_t a0, a1, a2, a3;                                                 \
            ldmx4(a0, a1, a2, a3, (tb) + ao);                                        \
            _Pragma("unroll")                                                        \
            for (int nf = 0; nf < 4; nf++)                                           \
                mma16816(acc[mf][nf], a0, a1, a2, a3, bh0[nf], bh1[nf]);             \
            _Pragma("unroll")                                                        \
            for (int nf = 0; nf < 4; nf++)                                           \
                mma16816(acc[mf][nf], a0, a1, a2, a3, bl0[nf], bl1[nf]);             \
            ldmx4(a0, a1, a2, a3, (tb) + 8192 + ao);                                 \
            _Pragma("unroll")                                                        \
            for (int nf = 0; nf < 4; nf++)                                           \
                mma16816(acc[mf][nf], a0, a1, a2, a3, bh0[nf], bh1[nf]);             \
        }                                                                            \
    }

#define HMMA_MAINLOOP()                                                              \
    loadTile(0, 0); cp_commit();                                                     \
    loadTile(1, 32); cp_commit();                                                    \
    for (int kt = 0; kt < NIT; kt++) {                                               \
        if (kt == NIT - 1) cp_wait<0>(); else cp_wait<1>();                          \
        __syncthreads();                                                             \
        if (kt + 2 < NIT) { loadTile((kt + 2) % 3, (kt + 2) * 32); cp_commit(); }    \
        uint32_t tb = sb + (uint32_t)((kt % 3) * 32768);                             \
        HMMA_COMPUTE(tb)                                                             \
    }

#define HMMA_PROLOGUE()                                                              \
    extern __shared__ char smem[];                                                   \
    uint32_t sb = smem_u32(smem);                                                    \
    const int tid = threadIdx.x;                                                     \
    const int rowStart = blockIdx.y * 128, colStart = blockIdx.x * 128;              \
    const int warp = tid >> 5, lane = tid & 31;                                      \
    const int wm = (warp & 1) * 64, wn = (warp >> 1) * 32;                           \
    const int ldRow = tid >> 1;                                                      \
    const int ldC0 = (tid & 1) * 2;                                                  \
    const uint32_t so0 = swz(ldRow, ldC0);                                           \
    const uint32_t so1 = swz(ldRow, ldC0 + 1);                                       \
    const int rA = lane & 15, khA = lane >> 4;                                       \
    const int rB = lane & 7, khB = (lane >> 3) & 1;                                  \
    float acc[4][4][4];                                                              \
    _Pragma("unroll")                                                                \
    for (int i = 0; i < 4; i++)                                                      \
        _Pragma("unroll")                                                            \
        for (int j = 0; j < 4; j++)                                                  \
            _Pragma("unroll")                                                        \
            for (int c = 0; c < 4; c++) acc[i][j][c] = 0.f;

#define QKV_EPILOGUE(isV)                                                            \
    {                                                                                \
        const int g = lane >> 2, q4 = lane & 3;                                      \
        const float coef = -0.034603417655075f;                                      \
        _Pragma("unroll")                                                            \
        for (int nf = 0; nf < 4; nf++) {                                             \
            int c = colStart + wn + 8 * nf + 2 * q4;                                 \
            float bx = bias[c], by = bias[c + 1];                                    \
            _Pragma("unroll")                                                        \
            for (int mf = 0; mf < 4; mf++) {                                         \
                int r0 = rowStart + wm + 16 * mf + g;                                \
                float v0 = acc[mf][nf][0] + bx;                                      \
                float v1 = acc[mf][nf][1] + by;                                      \
                float v2 = acc[mf][nf][2] + bx;                                      \
                float v3 = acc[mf][nf][3] + by;                                      \
                if (!(isV)) {                                                        \
                    float theta = exp2f(coef * (float)(c >> 1));                     \
                    int s0 = r0 & (SS - 1);                                          \
                    float sn, cs;                                                    \
                    sincosf((float)s0 * theta, &sn, &cs);                            \
                    float x0 = v0 * cs - v1 * sn, x1 = v1 * cs + v0 * sn;            \
                    sincosf((float)(s0 + 8) * theta, &sn, &cs);                      \
                    float x2 = v2 * cs - v3 * sn, x3 = v3 * cs + v2 * sn;            \
                    store_split2(Oh, Ol, (size_t)r0 * 768 + c, x0, x1);              \
                    store_split2(Oh, Ol, (size_t)(r0 + 8) * 768 + c, x2, x3);        \
                } else {                                                             \
                    int bb = r0 >> 9, s0 = r0 & (SS - 1);                            \
                    split1(v0, Oh, Ol, ((size_t)(bb * 768 + c)) * 512 + s0);         \
                    split1(v1, Oh, Ol, ((size_t)(bb * 768 + c + 1)) * 512 + s0);     \
                    split1(v2, Oh, Ol, ((size_t)(bb * 768 + c)) * 512 + s0 + 8);     \
                    split1(v3, Oh, Ol, ((size_t)(bb * 768 + c + 1)) * 512 + s0 + 8); \
                }                                                                    \
            }                                                                        \
        }                                                                            \
    }

// ======================= projection GEMM =======================
// EPI: 0=fp32+bias ; 5=silu+split ; 6=fp32+bias AND split
template <int EPI, int CAT>
__global__ void __launch_bounds__(256, 2) hmma_gemm_kernel(
    const bf16* __restrict__ A1h, const bf16* __restrict__ A1l,
    const bf16* __restrict__ A2h, const bf16* __restrict__ A2l,
    const bf16* __restrict__ Wh, const bf16* __restrict__ Wl,
    const float* __restrict__ bias, float* __restrict__ C,
    bf16* __restrict__ Oh, bf16* __restrict__ Ol, int K)
{
    HMMA_PROLOGUE()
    const int NIT = K / 32;

    auto loadTile = [&](int buf, int k0) {
        uint32_t base = sb + buf * 32768;
        int kk = k0 + ldC0 * 8;
        const bf16 *ph, *pl; size_t aoff;
        if (!CAT) {
            ph = A1h; pl = A1l; aoff = (size_t)(rowStart + ldRow) * K + kk;
        } else if (k0 < 768) {
            ph = A1h; pl = A1l; aoff = (size_t)(rowStart + ldRow) * 768 + kk;
        } else {
            ph = A2h; pl = A2l; aoff = (size_t)(rowStart + ldRow) * 768 + (kk - 768);
        }
        cp_async16(base + so0, ph + aoff);
        cp_async16(base + so1, ph + aoff + 8);
        cp_async16(base + 8192 + so0, pl + aoff);
        cp_async16(base + 8192 + so1, pl + aoff + 8);
        size_t boff = (size_t)(colStart + ldRow) * K + kk;
        cp_async16(base + 16384 + so0, Wh + boff);
        cp_async16(base + 16384 + so1, Wh + boff + 8);
        cp_async16(base + 24576 + so0, Wl + boff);
        cp_async16(base + 24576 + so1, Wl + boff + 8);
    };

    HMMA_MAINLOOP()

    const int g = lane >> 2, q4 = lane & 3;
    #pragma unroll
    for (int nf = 0; nf < 4; nf++) {
        int c = colStart + wn + 8 * nf + 2 * q4;
        float bx = bias[c], by = bias[c + 1];
        #pragma unroll
        for (int mf = 0; mf < 4; mf++) {
            int r0 = rowStart + wm + 16 * mf + g;
            float v0 = acc[mf][nf][0] + bx;
            float v1 = acc[mf][nf][1] + by;
            float v2 = acc[mf][nf][2] + bx;
            float v3 = acc[mf][nf][3] + by;
            if (EPI == 0 || EPI == 6) {
                *(float2*)(C + (size_t)r0 * 768 + c) = make_float2(v0, v1);
                *(float2*)(C + (size_t)(r0 + 8) * 768 + c) = make_float2(v2, v3);
                if (EPI == 6) {
                    store_split2(Oh, Ol, (size_t)r0 * 768 + c, v0, v1);
                    store_split2(Oh, Ol, (size_t)(r0 + 8) * 768 + c, v2, v3);
                }
            } else { // silu + split
                v0 *= 1.f / (1.f + __expf(-v0));
                v1 *= 1.f / (1.f + __expf(-v1));
                v2 *= 1.f / (1.f + __expf(-v2));
                v3 *= 1.f / (1.f + __expf(-v3));
                store_split2(Oh, Ol, (size_t)r0 * 768 + c, v0, v1);
                store_split2(Oh, Ol, (size_t)(r0 + 8) * 768 + c, v2, v3);
            }
        }
    }
}

// ======================= fused dual-attention QKV =======================
__global__ void __launch_bounds__(256, 2) hmma_qkv2_kernel(
    const bf16* __restrict__ aq0h, const bf16* __restrict__ aq0l,
    const bf16* __restrict__ akv0h, const bf16* __restrict__ akv0l,
    const bf16* __restrict__ aq1h, const bf16* __restrict__ aq1l,
    const bf16* __restrict__ akv1h, const bf16* __restrict__ akv1l,
    const bf16* __restrict__ w0h, const bf16* __restrict__ w0l,
    const bf16* __restrict__ w1h, const bf16* __restrict__ w1l,
    const float* __restrict__ bq0, const float* __restrict__ bk0, const float* __restrict__ bv0,
    const float* __restrict__ bq1, const float* __restrict__ bk1, const float* __restrict__ bv1,
    bf16* __restrict__ q0h, bf16* __restrict__ q0l,
    bf16* __restrict__ k0h, bf16* __restrict__ k0l,
    bf16* __restrict__ vt0h, bf16* __restrict__ vt0l,
    bf16* __restrict__ q1h, bf16* __restrict__ q1l,
    bf16* __restrict__ k1h, bf16* __restrict__ k1l,
    bf16* __restrict__ vt1h, bf16* __restrict__ vt1l)
{
    HMMA_PROLOGUE()
    const int z = blockIdx.z;
    const int att = z / 3, c3 = z - att * 3;
    const bf16* Ah = (c3 == 0) ? (att ? aq1h : aq0h) : (att ? akv1h : akv0h);
    const bf16* Al = (c3 == 0) ? (att ? aq1l : aq0l) : (att ? akv1l : akv0l);
    const bf16* Wh = (att ? w1h : w0h) + (size_t)c3 * WSZ;
    const bf16* Wl = (att ? w1l : w0l) + (size_t)c3 * WSZ;
    const float* bias = att ? (c3 == 0 ? bq1 : c3 == 1 ? bk1 : bv1)
                            : (c3 == 0 ? bq0 : c3 == 1 ? bk0 : bv0);
    bf16* Oh = att ? (c3 == 0 ? q1h : c3 == 1 ? k1h : vt1h)
                   : (c3 == 0 ? q0h : c3 == 1 ? k0h : vt0h);
    bf16* Ol = att ? (c3 == 0 ? q1l : c3 == 1 ? k1l : vt1l)
                   : (c3 == 0 ? q0l : c3 == 1 ? k0l : vt0l);

    const int NIT = 24;
    auto loadTile = [&](int buf, int k0) {
        uint32_t base = sb + buf * 32768;
        int kk = k0 + ldC0 * 8;
        size_t aoff = (size_t)(rowStart + ldRow) * 768 + kk;
        cp_async16(base + so0, Ah + aoff);
        cp_async16(base + so1, Ah + aoff + 8);
        cp_async16(base + 8192 + so0, Al + aoff);
        cp_async16(base + 8192 + so1, Al + aoff + 8);
        size_t boff = (size_t)(colStart + ldRow) * 768 + kk;
        cp_async16(base + 16384 + so0, Wh + boff);
        cp_async16(base + 16384 + so1, Wh + boff + 8);
        cp_async16(base + 24576 + so0, Wl + boff);
        cp_async16(base + 24576 + so1, Wl + boff + 8);
    };
    HMMA_MAINLOOP()
    QKV_EPILOGUE(c3 == 2)
}

// single-attention QKV (stage 3)
__global__ void __launch_bounds__(256, 2) hmma_qkv_kernel(
    const bf16* __restrict__ Aqh, const bf16* __restrict__ Aql,
    const bf16* __restrict__ Akvh, const bf16* __restrict__ Akvl,
    const bf16* __restrict__ Wbh, const bf16* __restrict__ Wbl,
    const float* __restrict__ bq, const float* __restrict__ bk, const float* __restrict__ bv,
    bf16* __restrict__ Qh, bf16* __restrict__ Ql2,
    bf16* __restrict__ Kh, bf16* __restrict__ Kl,
    bf16* __restrict__ Vth, bf16* __restrict__ Vtl)
{
    HMMA_PROLOGUE()
    const int z = blockIdx.z;
    const bf16* Ah = (z == 0) ? Aqh : Akvh;
    const bf16* Al = (z == 0) ? Aql : Akvl;
    const bf16* Wh = Wbh + (size_t)z * WSZ;
    const bf16* Wl = Wbl + (size_t)z * WSZ;
    const float* bias = (z == 0) ? bq : (z == 1) ? bk : bv;
    bf16* Oh = (z == 0) ? Qh : (z == 1) ? Kh : Vth;
    bf16* Ol = (z == 0) ? Ql2 : (z == 1) ? Kl : Vtl;

    const int NIT = 24;
    auto loadTile = [&](int buf, int k0) {
        uint32_t base = sb + buf * 32768;
        int kk = k0 + ldC0 * 8;
        size_t aoff = (size_t)(rowStart + ldRow) * 768 + kk;
        cp_async16(base + so0, Ah + aoff);
        cp_async16(base + so1, Ah + aoff + 8);
        cp_async16(base + 8192 + so0, Al + aoff);
        cp_async16(base + 8192 + so1, Al + aoff + 8);
        size_t boff = (size_t)(colStart + ldRow) * 768 + kk;
        cp_async16(base + 16384 + so0, Wh + boff);
        cp_async16(base + 16384 + so1, Wh + boff + 8);
        cp_async16(base + 24576 + so0, Wl + boff);
        cp_async16(base + 24576 + so1, Wl + boff + 8);
    };
    HMMA_MAINLOOP()
    QKV_EPILOGUE(z == 2)
}

// ======================= fused dual score =======================
__global__ void __launch_bounds__(256, 2) hmma_score2_kernel(
    const bf16* __restrict__ q0h, const bf16* __restrict__ q0l,
    const bf16* __restrict__ k0h, const bf16* __restrict__ k0l,
    const bf16* __restrict__ q1h, const bf16* __restrict__ q1l,
    const bf16* __restrict__ k1h, const bf16* __restrict__ k1l,
    float* __restrict__ Sc)
{
    HMMA_PROLOGUE()
    const int z = blockIdx.z;
    const int att = z >> 5, b = z & 31;
    const bf16* Qh = att ? q1h : q0h;
    const bf16* Ql = att ? q1l : q0l;
    const bf16* Kh = att ? k1h : k0h;
    const bf16* Kl = att ? k1l : k0l;

    const int NIT = 24;
    auto loadTile = [&](int buf, int k0) {
        uint32_t base = sb + buf * 32768;
        int kk = k0 + ldC0 * 8;
        size_t aoff = (size_t)(b * 512 + rowStart + ldRow) * 768 + kk;
        size_t boff = (size_t)(b * 512 + colStart + ldRow) * 768 + kk;
        cp_async16(base + so0, Qh + aoff);
        cp_async16(base + so1, Qh + aoff + 8);
        cp_async16(base + 8192 + so0, Ql + aoff);
        cp_async16(base + 8192 + so1, Ql + aoff + 8);
        cp_async16(base + 16384 + so0, Kh + boff);
        cp_async16(base + 16384 + so1, Kh + boff + 8);
        cp_async16(base + 24576 + so0, Kl + boff);
        cp_async16(base + 24576 + so1, Kl + boff + 8);
    };
    HMMA_MAINLOOP()

    float* C = Sc + (size_t)z * 262144;
    const int g = lane >> 2, q4 = lane & 3;
    #pragma unroll
    for (int nf = 0; nf < 4; nf++) {
        int c = colStart + wn + 8 * nf + 2 * q4;
        #pragma unroll
        for (int mf = 0; mf < 4; mf++) {
            int r0 = rowStart + wm + 16 * mf + g;
            *(float2*)(C + (size_t)r0 * 512 + c) =
                make_float2(8.f * acc[mf][nf][0], 8.f * acc[mf][nf][1]);
            *(float2*)(C + (size_t)(r0 + 8) * 512 + c) =
                make_float2(8.f * acc[mf][nf][2], 8.f * acc[mf][nf][3]);
        }
    }
}

// single-attention score (stage 3, H heads)
__global__ void __launch_bounds__(256, 2) hmma_score_kernel(
    const bf16* __restrict__ Qh, const bf16* __restrict__ Ql,
    const bf16* __restrict__ Kh, const bf16* __restrict__ Kl,
    float* __restrict__ Sc, int H, int hd)
{
    HMMA_PROLOGUE()
    const int z = blockIdx.z, b = z / H, h = z - b * H;
    const int NIT = hd / 32;
    auto loadTile = [&](int buf, int k0) {
        uint32_t base = sb + buf * 32768;
        int kk = k0 + ldC0 * 8;
        size_t aoff = (size_t)(b * 512 + rowStart + ldRow) * 768 + h * hd + kk;
        size_t boff = (size_t)(b * 512 + colStart + ldRow) * 768 + h * hd + kk;
        cp_async16(base + so0, Qh + aoff);
        cp_async16(base + so1, Qh + aoff + 8);
        cp_async16(base + 8192 + so0, Ql + aoff);
        cp_async16(base + 8192 + so1, Ql + aoff + 8);
        cp_async16(base + 16384 + so0, Kh + boff);
        cp_async16(base + 16384 + so1, Kh + boff + 8);
        cp_async16(base + 24576 + so0, Kl + boff);
        cp_async16(base + 24576 + so1, Kl + boff + 8);
    };
    HMMA_MAINLOOP()

    float* C = Sc + (size_t)z * 262144;
    const int g = lane >> 2, q4 = lane & 3;
    #pragma unroll
    for (int nf = 0; nf < 4; nf++) {
        int c = colStart + wn + 8 * nf + 2 * q4;
        #pragma unroll
        for (int mf = 0; mf < 4; mf++) {
            int r0 = rowStart + wm + 16 * mf + g;
            *(float2*)(C + (size_t)r0 * 512 + c) =
                make_float2(8.f * acc[mf][nf][0], 8.f * acc[mf][nf][1]);
            *(float2*)(C + (size_t)(r0 + 8) * 512 + c) =
                make_float2(8.f * acc[mf][nf][2], 8.f * acc[mf][nf][3]);
        }
    }
}

// ======================= fused dual PV =======================
__global__ void __launch_bounds__(256, 2) hmma_pv2_kernel(
    const bf16* __restrict__ Ph, const bf16* __restrict__ Pl,
    const bf16* __restrict__ vt0h, const bf16* __restrict__ vt0l,
    const bf16* __restrict__ vt1h, const bf16* __restrict__ vt1l,
    bf16* __restrict__ o0h, bf16* __restrict__ o0l,
    bf16* __restrict__ o1h, bf16* __restrict__ o1l)
{
    HMMA_PROLOGUE()
    const int z = blockIdx.z;
    const int att = z >> 5, b = z & 31;
    const bf16* Vth = att ? vt1h : vt0h;
    const bf16* Vtl = att ? vt1l : vt0l;
    bf16* Oh = att ? o1h : o0h;
    bf16* Ol = att ? o1l : o0l;

    const int NIT = 16;
    auto loadTile = [&](int buf, int k0) {
        uint32_t base = sb + buf * 32768;
        int kk = k0 + ldC0 * 8;
        size_t aoff = (size_t)z * 262144 + (size_t)(rowStart + ldRow) * 512 + kk;
        size_t boff = (size_t)(b * 768 + colStart + ldRow) * 512 + kk;
        cp_async16(base + so0, Ph + aoff);
        cp_async16(base + so1, Ph + aoff + 8);
        cp_async16(base + 8192 + so0, Pl + aoff);
        cp_async16(base + 8192 + so1, Pl + aoff + 8);
        cp_async16(base + 16384 + so0, Vth + boff);
        cp_async16(base + 16384 + so1, Vth + boff + 8);
        cp_async16(base + 24576 + so0, Vtl + boff);
        cp_async16(base + 24576 + so1, Vtl + boff + 8);
    };
    HMMA_MAINLOOP()

    const int g = lane >> 2, q4 = lane & 3;
    #pragma unroll
    for (int nf = 0; nf < 4; nf++) {
        int c = colStart + wn + 8 * nf + 2 * q4;
        #pragma unroll
        for (int mf = 0; mf < 4; mf++) {
            int r0 = b * 512 + rowStart + wm + 16 * mf + g;
            store_split2(Oh, Ol, (size_t)r0 * 768 + c, acc[mf][nf][0], acc[mf][nf][1]);
            store_split2(Oh, Ol, (size_t)(r0 + 8) * 768 + c, acc[mf][nf][2], acc[mf][nf][3]);
        }
    }
}

// single-attention PV (stage 3)
__global__ void __launch_bounds__(256, 2) hmma_pv_kernel(
    const bf16* __restrict__ Ph, const bf16* __restrict__ Pl,
    const bf16* __restrict__ Vth, const bf16* __restrict__ Vtl,
    bf16* __restrict__ Oh, bf16* __restrict__ Ol, int H, int hd)
{
    HMMA_PROLOGUE()
    const int z = blockIdx.z, b = z / H, h = z - b * H;
    const int NIT = 16;
    auto loadTile = [&](int buf, int k0) {
        uint32_t base = sb + buf * 32768;
        int kk = k0 + ldC0 * 8;
        size_t aoff = (size_t)z * 262144 + (size_t)(rowStart + ldRow) * 512 + kk;
        size_t boff = (size_t)(b * 768 + h * hd + colStart + ldRow) * 512 + kk;
        cp_async16(base + so0, Ph + aoff);
        cp_async16(base + so1, Ph + aoff + 8);
        cp_async16(base + 8192 + so0, Pl + aoff);
        cp_async16(base + 8192 + so1, Pl + aoff + 8);
        cp_async16(base + 16384 + so0, Vth + boff);
        cp_async16(base + 16384 + so1, Vth + boff + 8);
        cp_async16(base + 24576 + so0, Vtl + boff);
        cp_async16(base + 24576 + so1, Vtl + boff + 8);
    };
    HMMA_MAINLOOP()

    const int g = lane >> 2, q4 = lane & 3;
    #pragma unroll
    for (int nf = 0; nf < 4; nf++) {
        int cl = colStart + wn + 8 * nf + 2 * q4;
        if (cl < hd) {
            int c = h * hd + cl;
            #pragma unroll
            for (int mf = 0; mf < 4; mf++) {
                int r0 = b * 512 + rowStart + wm + 16 * mf + g;
                store_split2(Oh, Ol, (size_t)r0 * 768 + c, acc[mf][nf][0], acc[mf][nf][1]);
                store_split2(Oh, Ol, (size_t)(r0 + 8) * 768 + c, acc[mf][nf][2], acc[mf][nf][3]);
            }
        }
    }
}

// ======================= host =======================
extern "C" void kernel_launch(void* const* d_in, const int* in_sizes, int n_in,
                              void* d_out, int out_size)
{
    (void)n_in; (void)out_size;
    const float *text, *vtab, *atab;
    const float *aw[18];
    const float *fcw, *fcb, *f1w, *f1b, *f2w, *f2b, *catw, *catb;
    const int *vid, *aid;

    if (in_sizes[1] == MR) {
        text = (const float*)d_in[0];
        vid  = (const int*)d_in[1];
        aid  = (const int*)d_in[2];
        vtab = (const float*)d_in[3];
        atab = (const float*)d_in[4];
        for (int i = 0; i < 18; i++) aw[i] = (const float*)d_in[5 + i];
        fcw = (const float*)d_in[23]; fcb = (const float*)d_in[24];
        f1w = (const float*)d_in[25]; f1b = (const float*)d_in[26];
        f2w = (const float*)d_in[27]; f2b = (const float*)d_in[28];
        catw = (const float*)d_in[29]; catb = (const float*)d_in[30];
    } else {
        text = (const float*)d_in[0];
        vtab = (const float*)d_in[1];
        atab = (const float*)d_in[2];
        for (int i = 0; i < 18; i++) aw[i] = (const float*)d_in[3 + i];
        fcw = (const float*)d_in[21]; fcb = (const float*)d_in[22];
        f1w = (const float*)d_in[23]; f1b = (const float*)d_in[24];
        f2w = (const float*)d_in[25]; f2b = (const float*)d_in[26];
        catw = (const float*)d_in[27]; catb = (const float*)d_in[28];
        vid  = (const int*)d_in[29];
        aid  = (const int*)d_in[30];
    }

    cudaFuncSetAttribute(hmma_gemm_kernel<0,0>, cudaFuncAttributeMaxDynamicSharedMemorySize, HG_SMEM);
    cudaFuncSetAttribute(hmma_gemm_kernel<5,0>, cudaFuncAttributeMaxDynamicSharedMemorySize, HG_SMEM);
    cudaFuncSetAttribute(hmma_gemm_kernel<6,0>, cudaFuncAttributeMaxDynamicSharedMemorySize, HG_SMEM);
    cudaFuncSetAttribute(hmma_gemm_kernel<0,1>, cudaFuncAttributeMaxDynamicSharedMemorySize, HG_SMEM);
    cudaFuncSetAttribute(hmma_qkv_kernel, cudaFuncAttributeMaxDynamicSharedMemorySize, HG_SMEM);
    cudaFuncSetAttribute(hmma_qkv2_kernel, cudaFuncAttributeMaxDynamicSharedMemorySize, HG_SMEM);
    cudaFuncSetAttribute(hmma_score_kernel, cudaFuncAttributeMaxDynamicSharedMemorySize, HG_SMEM);
    cudaFuncSetAttribute(hmma_score2_kernel, cudaFuncAttributeMaxDynamicSharedMemorySize, HG_SMEM);
    cudaFuncSetAttribute(hmma_pv_kernel, cudaFuncAttributeMaxDynamicSharedMemorySize, HG_SMEM);
    cudaFuncSetAttribute(hmma_pv2_kernel, cudaFuncAttributeMaxDynamicSharedMemorySize, HG_SMEM);

    float *sc, *F1, *F2, *F3;
    bf16 *wth, *wtl, *cth, *ctl;
    bf16 *spt_h, *spt_l, *sev_h, *sev_l, *sea_h, *sea_l;
    bf16 *sq_h, *sq_l, *sk_h, *sk_l, *svt_h, *svt_l;
    bf16 *sq2_h, *sq2_l, *sk2_h, *sk2_l, *svt2_h, *svt2_l;
    bf16 *sp_h, *sp_l;
    bf16 *s1_h, *s1_l, *s2_h, *s2_l, *s3_h, *s3_l, *s4_h, *s4_l;
    bf16 *c1_h, *c1_l, *c2_h, *c2_l, *c3_h, *c3_l;
    cudaGetSymbolAddress((void**)&sc, g_sc);
    cudaGetSymbolAddress((void**)&F1, g_F1);
    cudaGetSymbolAddress((void**)&F2, g_F2);
    cudaGetSymbolAddress((void**)&F3, g_F3);
    cudaGetSymbolAddress((void**)&wth, g_wth);
    cudaGetSymbolAddress((void**)&wtl, g_wtl);
    cudaGetSymbolAddress((void**)&cth, g_cth);
    cudaGetSymbolAddress((void**)&ctl, g_ctl);
    cudaGetSymbolAddress((void**)&spt_h, g_spt_h); cudaGetSymbolAddress((void**)&spt_l, g_spt_l);
    cudaGetSymbolAddress((void**)&sev_h, g_sev_h); cudaGetSymbolAddress((void**)&sev_l, g_sev_l);
    cudaGetSymbolAddress((void**)&sea_h, g_sea_h); cudaGetSymbolAddress((void**)&sea_l, g_sea_l);
    cudaGetSymbolAddress((void**)&sq_h, g_sq_h);   cudaGetSymbolAddress((void**)&sq_l, g_sq_l);
    cudaGetSymbolAddress((void**)&sk_h, g_sk_h);   cudaGetSymbolAddress((void**)&sk_l, g_sk_l);
    cudaGetSymbolAddress((void**)&svt_h, g_svt_h); cudaGetSymbolAddress((void**)&svt_l, g_svt_l);
    cudaGetSymbolAddress((void**)&sq2_h, g_sq2_h); cudaGetSymbolAddress((void**)&sq2_l, g_sq2_l);
    cudaGetSymbolAddress((void**)&sk2_h, g_sk2_h); cudaGetSymbolAddress((void**)&sk2_l, g_sk2_l);
    cudaGetSymbolAddress((void**)&svt2_h, g_svt2_h); cudaGetSymbolAddress((void**)&svt2_l, g_svt2_l);
    cudaGetSymbolAddress((void**)&sp_h, g_sp_h);   cudaGetSymbolAddress((void**)&sp_l, g_sp_l);
    cudaGetSymbolAddress((void**)&s1_h, g_s1_h);   cudaGetSymbolAddress((void**)&s1_l, g_s1_l);
    cudaGetSymbolAddress((void**)&s2_h, g_s2_h);   cudaGetSymbolAddress((void**)&s2_l, g_s2_l);
    cudaGetSymbolAddress((void**)&s3_h, g_s3_h);   cudaGetSymbolAddress((void**)&s3_l, g_s3_l);
    cudaGetSymbolAddress((void**)&s4_h, g_s4_h);   cudaGetSymbolAddress((void**)&s4_l, g_s4_l);
    cudaGetSymbolAddress((void**)&c1_h, g_c1_h);   cudaGetSymbolAddress((void**)&c1_l, g_c1_l);
    cudaGetSymbolAddress((void**)&c2_h, g_c2_h);   cudaGetSymbolAddress((void**)&c2_l, g_c2_l);
    cudaGetSymbolAddress((void**)&c3_h, g_c3_h);   cudaGetSymbolAddress((void**)&c3_l, g_c3_l);

    const int EW = (NEL + 255) / 256;
    const int SW = (NEL / 2 + 255) / 256;
    const dim3 gHG(6, 128);

    // -------- weight prep --------
    const float* wsrc[12] = { aw[0], aw[2], aw[4], aw[6], aw[8], aw[10],
                              aw[12], aw[14], aw[16], fcw, f1w, f2w };
    for (int i = 0; i < 12; i++)
        wsplit_kernel<<<dim3(24, 24), 256>>>(wsrc[i], wth + (size_t)i * WSZ, wtl + (size_t)i * WSZ, 768);
    wsplit_kernel<<<dim3(48, 24), 256>>>(catw, cth, ctl, 1536);

    auto GEMM_F = [&](const bf16* Ah, const bf16* Al, int wi, const float* bi, float* Cc) {
        hmma_gemm_kernel<0,0><<<gHG, 256, HG_SMEM>>>(Ah, Al, nullptr, nullptr,
            wth + (size_t)wi * WSZ, wtl + (size_t)wi * WSZ, bi, Cc, nullptr, nullptr, 768);
    };
    auto GEMM_FS = [&](const bf16* Ah, const bf16* Al, int wi, const float* bi, float* Cc,
                       bf16* oh, bf16* ol) {
        hmma_gemm_kernel<6,0><<<gHG, 256, HG_SMEM>>>(Ah, Al, nullptr, nullptr,
            wth + (size_t)wi * WSZ, wtl + (size_t)wi * WSZ, bi, Cc, oh, ol, 768);
    };
    auto GEMM_SILU = [&](const bf16* Ah, const bf16* Al, int wi, const float* bi, bf16* oh, bf16* ol) {
        hmma_gemm_kernel<5,0><<<gHG, 256, HG_SMEM>>>(Ah, Al, nullptr, nullptr,
            wth + (size_t)wi * WSZ, wtl + (size_t)wi * WSZ, bi, nullptr, oh, ol, 768);
    };
    auto CATGEMM = [&](const bf16* A1h, const bf16* A1l, const bf16* A2h, const bf16* A2l,
                       const float* bi, float* Cc) {
        hmma_gemm_kernel<0,1><<<gHG, 256, HG_SMEM>>>(A1h, A1l, A2h, A2l, cth, ctl, bi, Cc,
                                                     nullptr, nullptr, 1536);
    };
    auto ATT2 = [&](const bf16* q0h_, const bf16* q0l_, const bf16* kv0h_, const bf16* kv0l_,
                    const bf16* q1h_, const bf16* q1l_, const bf16* kv1h_, const bf16* kv1l_,
                    bf16* o0h, bf16* o0l, bf16* o1h, bf16* o1l) {
        hmma_qkv2_kernel<<<dim3(6, 128, 6), 256, HG_SMEM>>>(
            q0h_, q0l_, kv0h_, kv0l_, q1h_, q1l_, kv1h_, kv1l_,
            wth, wtl, wth + 3 * (size_t)WSZ, wtl + 3 * (size_t)WSZ,
            aw[1], aw[3], aw[5], aw[7], aw[9], aw[11],
            sq_h, sq_l, sk_h, sk_l, svt_h, svt_l,
            sq2_h, sq2_l, sk2_h, sk2_l, svt2_h, svt2_l);
        hmma_score2_kernel<<<dim3(4, 4, 64), 256, HG_SMEM>>>(
            sq_h, sq_l, sk_h, sk_l, sq2_h, sq2_l, sk2_h, sk2_l, sc);
        softmax_split_kernel<<<2 * MR, 256>>>(sc, sp_h, sp_l);
        hmma_pv2_kernel<<<dim3(6, 4, 64), 256, HG_SMEM>>>(
            sp_h, sp_l, svt_h, svt_l, svt2_h, svt2_l, o0h, o0l, o1h, o1l);
    };
    auto FFN = [&](float* x) {   // scratch: c1, c2 only
        gate_split_kernel<<<MR, 256>>>(x, c1_h, c1_l);
        GEMM_SILU(c1_h, c1_l, 10, f1b, c2_h, c2_l);
        GEMM_F(c2_h, c2_l, 11, f2b, x);
    };

    // -------- forward --------
    asplit_kernel<<<SW, 256>>>(text, spt_h, spt_l);
    embed_split_kernel<<<EW, 256>>>(vtab, vid, sev_h, sev_l);
    embed_split_kernel<<<EW, 256>>>(atab, aid, sea_h, sea_l);

    // stage 1: visual_=hv(text,emb_v), acoustic_=ha(text,emb_a)
    ATT2(spt_h, spt_l, sev_h, sev_l, spt_h, spt_l, sea_h, sea_l, s1_h, s1_l, s2_h, s2_l);
    CATGEMM(s1_h, s1_l, s2_h, s2_l, catb, F1);
    // FFN(F1) with fused split of final output into DEDICATED c3 (survives stage 2)
    gate_split_kernel<<<MR, 256>>>(F1, c1_h, c1_l);
    GEMM_SILU(c1_h, c1_l, 10, f1b, c2_h, c2_l);
    GEMM_FS(c2_h, c2_l, 11, f2b, F1, c3_h, c3_l);   // F1 fp32 + split -> c3

    // stage 2: v=hv(visual_,acoustic_), a=ha(acoustic_,visual_)
    ATT2(s1_h, s1_l, s2_h, s2_l, s2_h, s2_l, s1_h, s1_l, s3_h, s3_l, s4_h, s4_l);
    CATGEMM(s3_h, s3_l, s4_h, s4_l, catb, F2);
    FFN(F2);   // uses c1/c2 — c3 untouched

    // stage 3: F3 = mh8(F1, text) @ fcw + fcb, then FFN   (c3 = split(F1))
    hmma_qkv_kernel<<<dim3(6, 128, 3), 256, HG_SMEM>>>(
        c3_h, c3_l, spt_h, spt_l,
        wth + 6 * (size_t)WSZ, wtl + 6 * (size_t)WSZ,
        aw[13], aw[15], aw[17], sq_h, sq_l, sk_h, sk_l, svt_h, svt_l);
    hmma_score_kernel<<<dim3(4, 4, 256), 256, HG_SMEM>>>(sq_h, sq_l, sk_h, sk_l, sc, 8, 96);
    softmax_split_kernel<<<BB * 8 * SS, 256>>>(sc, sp_h, sp_l);
    hmma_pv_kernel<<<dim3(1, 4, 256), 256, HG_SMEM>>>(sp_h, sp_l, svt_h, svt_l, c2_h, c2_l, 8, 96);
    GEMM_F(c2_h, c2_l, 9, fcb, F3);
    FFN(F3);

    // out = gate(text + F1 + F2 + F3)
    gate4_kernel<<<MR, 256>>>(text, F1, F2, F3, (float*)d_out);
}

// round 17
// speedup vs baseline: 1.0533x; 1.0042x over previous
#include <cuda_runtime.h>
#include <cuda_bf16.h>
#include <math.h>
#include <stdint.h>

#define DM 768
#define BB 32
#define SS 512
#define MR (BB*SS)          // 16384 rows
#define NEL (MR*DM)         // 12582912

typedef __nv_bfloat16 bf16;

// ======================= helpers =======================
__device__ __forceinline__ uint32_t smem_u32(const void* p) {
    uint32_t a;
    asm("{ .reg .u64 t; cvta.to.shared.u64 t, %1; cvt.u32.u64 %0, t; }" : "=r"(a) : "l"(p));
    return a;
}
__device__ __forceinline__ void cp_async16(uint32_t dst, const void* src) {
    asm volatile("cp.async.cg.shared.global [%0],[%1],16;" :: "r"(dst), "l"(src));
}
__device__ __forceinline__ void cp_commit() { asm volatile("cp.async.commit_group;"); }
template <int N>
__device__ __forceinline__ void cp_wait() { asm volatile("cp.async.wait_group %0;" :: "n"(N)); }
__device__ __forceinline__ void ldmx4(uint32_t& a0, uint32_t& a1, uint32_t& a2, uint32_t& a3, uint32_t addr) {
    asm volatile("ldmatrix.sync.aligned.m8n8.x4.shared.b16 {%0,%1,%2,%3},[%4];"
                 : "=r"(a0), "=r"(a1), "=r"(a2), "=r"(a3) : "r"(addr));
}
__device__ __forceinline__ void ldmx2(uint32_t& b0, uint32_t& b1, uint32_t addr) {
    asm volatile("ldmatrix.sync.aligned.m8n8.x2.shared.b16 {%0,%1},[%2];"
                 : "=r"(b0), "=r"(b1) : "r"(addr));
}
__device__ __forceinline__ void mma16816(float* c, uint32_t a0, uint32_t a1, uint32_t a2, uint32_t a3,
                                         uint32_t b0, uint32_t b1) {
    asm volatile("mma.sync.aligned.m16n8k16.row.col.f32.bf16.bf16.f32 "
                 "{%0,%1,%2,%3},{%4,%5,%6,%7},{%8,%9},{%0,%1,%2,%3};"
                 : "+f"(c[0]), "+f"(c[1]), "+f"(c[2]), "+f"(c[3])
                 : "r"(a0), "r"(a1), "r"(a2), "r"(a3), "r"(b0), "r"(b1));
}
__device__ __forceinline__ uint32_t swz(int row, int chunk) {
    return (uint32_t)(row * 64 + ((chunk ^ ((row >> 1) & 3)) << 4));
}
__device__ __forceinline__ void store_split2(bf16* Oh, bf16* Ol, size_t idx, float a, float b) {
    bf16 ha = __float2bfloat16(a);
    bf16 hb = __float2bfloat16(b);
    __nv_bfloat162 hh; hh.x = ha; hh.y = hb;
    __nv_bfloat162 ll;
    ll.x = __float2bfloat16(a - __bfloat162float(ha));
    ll.y = __float2bfloat16(b - __bfloat162float(hb));
    *(__nv_bfloat162*)(Oh + idx) = hh;
    *(__nv_bfloat162*)(Ol + idx) = ll;
}
__device__ __forceinline__ void split1(float x, bf16* h, bf16* l, size_t idx) {
    bf16 hh = __float2bfloat16(x);
    h[idx] = hh;
    l[idx] = __float2bfloat16(x - __bfloat162float(hh));
}

// ======================= scratch =======================
static __device__ float g_sc[67108864];
static __device__ float g_F1[NEL];
static __device__ float g_F2[NEL];
static __device__ float g_F3[NEL];

#define WSZ (768*768)
static __device__ bf16 g_wth[12 * WSZ];
static __device__ bf16 g_wtl[12 * WSZ];
static __device__ bf16 g_cth[768 * 1536];
static __device__ bf16 g_ctl[768 * 1536];

static __device__ bf16 g_spt_h[NEL], g_spt_l[NEL];
static __device__ bf16 g_sev_h[NEL], g_sev_l[NEL];
static __device__ bf16 g_sea_h[NEL], g_sea_l[NEL];
static __device__ bf16 g_sq_h[NEL],  g_sq_l[NEL];
static __device__ bf16 g_sk_h[NEL],  g_sk_l[NEL];
static __device__ bf16 g_svt_h[NEL + 65536], g_svt_l[NEL + 65536];
static __device__ bf16 g_sq2_h[NEL],  g_sq2_l[NEL];
static __device__ bf16 g_sk2_h[NEL],  g_sk2_l[NEL];
static __device__ bf16 g_svt2_h[NEL + 65536], g_svt2_l[NEL + 65536];
static __device__ bf16 g_sp_h[67108864], g_sp_l[67108864];
static __device__ bf16 g_s1_h[NEL], g_s1_l[NEL];
static __device__ bf16 g_s2_h[NEL], g_s2_l[NEL];
static __device__ bf16 g_s3_h[NEL], g_s3_l[NEL];
static __device__ bf16 g_s4_h[NEL], g_s4_l[NEL];
static __device__ bf16 g_c1_h[NEL], g_c1_l[NEL];
static __device__ bf16 g_c2_h[NEL], g_c2_l[NEL];
static __device__ bf16 g_c3_h[NEL], g_c3_l[NEL];   // dedicated: split(F1), survives stage 2

// ======================= elementwise =======================
__global__ void __launch_bounds__(256) asplit_kernel(
    const float* __restrict__ x, bf16* __restrict__ h, bf16* __restrict__ l)
{
    int i = blockIdx.x * 256 + threadIdx.x;
    if (i >= NEL / 2) return;
    float2 v = ((const float2*)x)[i];
    store_split2(h, l, (size_t)i * 2, v.x, v.y);
}

__global__ void __launch_bounds__(256) embed_split_kernel(
    const float* __restrict__ tab, const int* __restrict__ ids,
    bf16* __restrict__ oh, bf16* __restrict__ ol)
{
    int i = blockIdx.x * 256 + threadIdx.x;
    if (i >= NEL) return;
    int row = i / DM;
    int d = i - row * DM;
    split1(tab[(size_t)ids[row] * DM + d], oh, ol, i);
}

__global__ void __launch_bounds__(256) wsplit_kernel(
    const float* __restrict__ W, bf16* __restrict__ Th, bf16* __restrict__ Tl, int K)
{
    __shared__ float t[32][33];
    int k0 = blockIdx.x * 32, n0 = blockIdx.y * 32;
    int tx = threadIdx.x & 31, ty = threadIdx.x >> 5;
    #pragma unroll
    for (int i = 0; i < 32; i += 8)
        t[ty + i][tx] = W[(size_t)(k0 + ty + i) * 768 + n0 + tx];
    __syncthreads();
    #pragma unroll
    for (int i = 0; i < 32; i += 8)
        split1(t[tx][ty + i], Th, Tl, (size_t)(n0 + ty + i) * K + k0 + tx);
}

__global__ void __launch_bounds__(256) softmax_split_kernel(
    const float* __restrict__ x, bf16* __restrict__ ph, bf16* __restrict__ pl)
{
    __shared__ float shm[8];
    __shared__ float shs[8];
    size_t row = blockIdx.x;
    const float* p = x + row * 512;
    int t = threadIdx.x;
    int lane = t & 31, wid = t >> 5;

    float a = p[t], b = p[t + 256];
    float m = fmaxf(a, b);
    #pragma unroll
    for (int o = 16; o; o >>= 1) m = fmaxf(m, __shfl_xor_sync(0xffffffffu, m, o));
    if (lane == 0) shm[wid] = m;
    __syncthreads();
    float m2 = shm[0];
    #pragma unroll
    for (int i = 1; i < 8; i++) m2 = fmaxf(m2, shm[i]);

    float e0 = __expf(a - m2), e1 = __expf(b - m2);
    float s = e0 + e1;
    #pragma unroll
    for (int o = 16; o; o >>= 1) s += __shfl_xor_sync(0xffffffffu, s, o);
    if (lane == 0) shs[wid] = s;
    __syncthreads();
    float s2 = 0.f;
    #pragma unroll
    for (int i = 0; i < 8; i++) s2 += shs[i];
    float inv = 1.f / s2;
    split1(e0 * inv, ph, pl, row * 512 + t);
    split1(e1 * inv, ph, pl, row * 512 + t + 256);
}

__global__ void __launch_bounds__(256) gate4_kernel(
    const float* __restrict__ t0, const float* __restrict__ f1,
    const float* __restrict__ f2, const float* __restrict__ f3,
    float* __restrict__ out)
{
    __shared__ float shm[8];
    __shared__ float shs[8];
    size_t row = blockIdx.x;
    size_t base = row * 768;
    float* q = out + base;
    int t = threadIdx.x;
    int lane = t & 31, wid = t >> 5;

    float a = t0[base + t]       + f1[base + t]       + f2[base + t]       + f3[base + t];
    float b = t0[base + t + 256] + f1[base + t + 256] + f2[base + t + 256] + f3[base + t + 256];
    float c = t0[base + t + 512] + f1[base + t + 512] + f2[base + t + 512] + f3[base + t + 512];
    float m = fmaxf(fmaxf(a, b), c);
    #pragma unroll
    for (int o = 16; o; o >>= 1) m = fmaxf(m, __shfl_xor_sync(0xffffffffu, m, o));
    if (lane == 0) shm[wid] = m;
    __syncthreads();
    float m2 = shm[0];
    #pragma unroll
    for (int i = 1; i < 8; i++) m2 = fmaxf(m2, shm[i]);

    float e0 = __expf(a - m2), e1 = __expf(b - m2), e2 = __expf(c - m2);
    float s = e0 + e1 + e2;
    #pragma unroll
    for (int o = 16; o; o >>= 1) s += __shfl_xor_sync(0xffffffffu, s, o);
    if (lane == 0) shs[wid] = s;
    __syncthreads();
    float s2 = 0.f;
    #pragma unroll
    for (int i = 0; i < 8; i++) s2 += shs[i];
    float inv = 1.f / s2;
    q[t]       = a + a * e0 * inv;
    q[t + 256] = b + b * e1 * inv;
    q[t + 512] = c + c * e2 * inv;
}

__global__ void __launch_bounds__(256) gate_split_kernel(
    const float* __restrict__ in, bf16* __restrict__ oh, bf16* __restrict__ ol)
{
    __shared__ float shm[8];
    __shared__ float shs[8];
    size_t row = blockIdx.x;
    const float* p = in + row * 768;
    int t = threadIdx.x;
    int lane = t & 31, wid = t >> 5;

    float a = p[t], b = p[t + 256], c = p[t + 512];
    float m = fmaxf(fmaxf(a, b), c);
    #pragma unroll
    for (int o = 16; o; o >>= 1) m = fmaxf(m, __shfl_xor_sync(0xffffffffu, m, o));
    if (lane == 0) shm[wid] = m;
    __syncthreads();
    float m2 = shm[0];
    #pragma unroll
    for (int i = 1; i < 8; i++) m2 = fmaxf(m2, shm[i]);

    float e0 = __expf(a - m2), e1 = __expf(b - m2), e2 = __expf(c - m2);
    float s = e0 + e1 + e2;
    #pragma unroll
    for (int o = 16; o; o >>= 1) s += __shfl_xor_sync(0xffffffffu, s, o);
    if (lane == 0) shs[wid] = s;
    __syncthreads();
    float s2 = 0.f;
    #pragma unroll
    for (int i = 0; i < 8; i++) s2 += shs[i];
    float inv = 1.f / s2;
    split1(a + a * e0 * inv, oh, ol, row * 768 + t);
    split1(b + b * e1 * inv, oh, ol, row * 768 + t + 256);
    split1(c + c * e2 * inv, oh, ol, row * 768 + t + 512);
}

// ======================= HMMA core (R7/R13 proven structure) =======================
#define HG_SMEM (3 * 32768)

#define HMMA_COMPUTE(tb)                                                             \
    _Pragma("unroll")                                                                \
    for (int kc = 0; kc < 2; kc++) {                                                 \
        uint32_t bh0[4], bh1[4], bl0[4], bl1[4];                                     \
        _Pragma("unroll")                                                            \
        for (int nf = 0; nf < 4; nf++) {                                             \
            int r = wn + 8 * nf + rB;                                                \
            uint32_t co = (uint32_t)(r * 64 + (((kc * 2 + khB) ^ ((r >> 1) & 3)) << 4)); \
            ldmx2(bh0[nf], bh1[nf], (tb) + 16384 + co);                              \
            ldmx2(bl0[nf], bl1[nf], (tb) + 24576 + co);                              \
        }                                                                            \
        _Pragma("unroll")                                                            \
        for (int mf = 0; mf < 4; mf++) {                                             \
            int r = wm + 16 * mf + rA;                                               \
            uint32_t ao = (uint32_t)(r * 64 + (((kc * 2 + khA) ^ ((r >> 1) & 3)) << 4)); \
            uint32_t a0, a1, a2, a3;                                                 \
            ldmx4(a0, a1, a2, a3, (tb) + ao);                                        \
            _Pragma("unroll")                                                        \
            for (int nf = 0; nf < 4; nf++)                                           \
                mma16816(acc[mf][nf], a0, a1, a2, a3, bh0[nf], bh1[nf]);             \
            _Pragma("unroll")                                                        \
            for (int nf = 0; nf < 4; nf++)                                           \
                mma16816(acc[mf][nf], a0, a1, a2, a3, bl0[nf], bl1[nf]);             \
            ldmx4(a0, a1, a2, a3, (tb) + 8192 + ao);                                 \
            _Pragma("unroll")                                                        \
            for (int nf = 0; nf < 4; nf++)                                           \
                mma16816(acc[mf][nf], a0, a1, a2, a3, bh0[nf], bh1[nf]);             \
        }                                                                            \
    }

// 96-wide variant: 3 n-frags, warp col tile = 24
#define HMMA_COMPUTE96(tb)                                                           \
    _Pragma("unroll")                                                                \
    for (int kc = 0; kc < 2; kc++) {                                                 \
        uint32_t bh0[3], bh1[3], bl0[3], bl1[3];                                     \
        _Pragma("unroll")                                                            \
        for (int nf = 0; nf < 3; nf++) {                                             \
            int r = wn + 8 * nf + rB;                                                \
            uint32_t co = (uint32_t)(r * 64 + (((kc * 2 + khB) ^ ((r >> 1) & 3)) << 4)); \
            ldmx2(bh0[nf], bh1[nf], (tb) + 16384 + co);                              \
            ldmx2(bl0[nf], bl1[nf], (tb) + 24576 + co);                              \
        }                                                                            \
        _Pragma("unroll")                                                            \
        for (int mf = 0; mf < 4; mf++) {                                             \
            int r = wm + 16 * mf + rA;                                               \
            uint32_t ao = (uint32_t)(r * 64 + (((kc * 2 + khA) ^ ((r >> 1) & 3)) << 4)); \
            uint32_t a0, a1, a2, a3;                                                 \
            ldmx4(a0, a1, a2, a3, (tb) + ao);                                        \
            _Pragma("unroll")                                                        \
            for (int nf = 0; nf < 3; nf++)                                           \
                mma16816(acc[mf][nf], a0, a1, a2, a3, bh0[nf], bh1[nf]);             \
            _Pragma("unroll")                                                        \
            for (int nf = 0; nf < 3; nf++)                                           \
                mma16816(acc[mf][nf], a0, a1, a2, a3, bl0[nf], bl1[nf]);             \
            ldmx4(a0, a1, a2, a3, (tb) + 8192 + ao);                                 \
            _Pragma("unroll")                                                        \
            for (int nf = 0; nf < 3; nf++)                                           \
                mma16816(acc[mf][nf], a0, a1, a2, a3, bh0[nf], bh1[nf]);             \
        }                                                                            \
    }

#define HMMA_MAINLOOP()                                                              \
    loadTile(0, 0); cp_commit();                                                     \
    loadTile(1, 32); cp_commit();                                                    \
    for (int kt = 0; kt < NIT; kt++) {                                               \
        if (kt == NIT - 1) cp_wait<0>(); else cp_wait<1>();                          \
        __syncthreads();                                                             \
        if (kt + 2 < NIT) { loadTile((kt + 2) % 3, (kt + 2) * 32); cp_commit(); }    \
        uint32_t tb = sb + (uint32_t)((kt % 3) * 32768);                             \
        HMMA_COMPUTE(tb)                                                             \
    }

#define HMMA_MAINLOOP96()                                                            \
    loadTile(0, 0); cp_commit();                                                     \
    loadTile(1, 32); cp_commit();                                                    \
    for (int kt = 0; kt < NIT; kt++) {                                               \
        if (kt == NIT - 1) cp_wait<0>(); else cp_wait<1>();                          \
        __syncthreads();                                                             \
        if (kt + 2 < NIT) { loadTile((kt + 2) % 3, (kt + 2) * 32); cp_commit(); }    \
        uint32_t tb = sb + (uint32_t)((kt % 3) * 32768);                             \
        HMMA_COMPUTE96(tb)                                                           \
    }

#define HMMA_PROLOGUE()                                                              \
    extern __shared__ char smem[];                                                   \
    uint32_t sb = smem_u32(smem);                                                    \
    const int tid = threadIdx.x;                                                     \
    const int rowStart = blockIdx.y * 128, colStart = blockIdx.x * 128;              \
    const int warp = tid >> 5, lane = tid & 31;                                      \
    const int wm = (warp & 1) * 64, wn = (warp >> 1) * 32;                           \
    const int ldRow = tid >> 1;                                                      \
    const int ldC0 = (tid & 1) * 2;                                                  \
    const uint32_t so0 = swz(ldRow, ldC0);                                           \
    const uint32_t so1 = swz(ldRow, ldC0 + 1);                                       \
    const int rA = lane & 15, khA = lane >> 4;                                       \
    const int rB = lane & 7, khB = (lane >> 3) & 1;                                  \
    float acc[4][4][4];                                                              \
    _Pragma("unroll")                                                                \
    for (int i = 0; i < 4; i++)                                                      \
        _Pragma("unroll")                                                            \
        for (int j = 0; j < 4; j++)                                                  \
            _Pragma("unroll")                                                        \
            for (int c = 0; c < 4; c++) acc[i][j][c] = 0.f;

// qscale: 8.f for Q (power-of-2 -> bit-exact fold of the score scale), 1.f for K
#define QKV_EPILOGUE(isV, qscale)                                                    \
    {                                                                                \
        const int g = lane >> 2, q4 = lane & 3;                                      \
        const float coef = -0.034603417655075f;                                      \
        _Pragma("unroll")                                                            \
        for (int nf = 0; nf < 4; nf++) {                                             \
            int c = colStart + wn + 8 * nf + 2 * q4;                                 \
            float bx = bias[c], by = bias[c + 1];                                    \
            _Pragma("unroll")                                                        \
            for (int mf = 0; mf < 4; mf++) {                                         \
                int r0 = rowStart + wm + 16 * mf + g;                                \
                float v0 = acc[mf][nf][0] + bx;                                      \
                float v1 = acc[mf][nf][1] + by;                                      \
                float v2 = acc[mf][nf][2] + bx;                                      \
                float v3 = acc[mf][nf][3] + by;                                      \
                if (!(isV)) {                                                        \
                    float theta = exp2f(coef * (float)(c >> 1));                     \
                    int s0 = r0 & (SS - 1);                                          \
                    float sn, cs;                                                    \
                    sincosf((float)s0 * theta, &sn, &cs);                            \
                    float x0 = (v0 * cs - v1 * sn) * (qscale);                       \
                    float x1 = (v1 * cs + v0 * sn) * (qscale);                       \
                    sincosf((float)(s0 + 8) * theta, &sn, &cs);                      \
                    float x2 = (v2 * cs - v3 * sn) * (qscale);                       \
                    float x3 = (v3 * cs + v2 * sn) * (qscale);                       \
                    store_split2(Oh, Ol, (size_t)r0 * 768 + c, x0, x1);              \
                    store_split2(Oh, Ol, (size_t)(r0 + 8) * 768 + c, x2, x3);        \
                } else {                                                             \
                    int bb = r0 >> 9, s0 = r0 & (SS - 1);                            \
                    split1(v0, Oh, Ol, ((size_t)(bb * 768 + c)) * 512 + s0);         \
                    split1(v1, Oh, Ol, ((size_t)(bb * 768 + c + 1)) * 512 + s0);     \
                    split1(v2, Oh, Ol, ((size_t)(bb * 768 + c)) * 512 + s0 + 8);     \
                    split1(v3, Oh, Ol, ((size_t)(bb * 768 + c + 1)) * 512 + s0 + 8); \
                }                                                                    \
            }                                                                        \
        }                                                                            \
    }

// ======================= projection GEMM =======================
// EPI: 0=fp32+bias ; 5=silu+split ; 6=fp32+bias AND split
template <int EPI, int CAT>
__global__ void __launch_bounds__(256, 2) hmma_gemm_kernel(
    const bf16* __restrict__ A1h, const bf16* __restrict__ A1l,
    const bf16* __restrict__ A2h, const bf16* __restrict__ A2l,
    const bf16* __restrict__ Wh, const bf16* __restrict__ Wl,
    const float* __restrict__ bias, float* __restrict__ C,
    bf16* __restrict__ Oh, bf16* __restrict__ Ol, int K)
{
    HMMA_PROLOGUE()
    const int NIT = K / 32;

    auto loadTile = [&](int buf, int k0) {
        uint32_t base = sb + buf * 32768;
        int kk = k0 + ldC0 * 8;
        const bf16 *ph, *pl; size_t aoff;
        if (!CAT) {
            ph = A1h; pl = A1l; aoff = (size_t)(rowStart + ldRow) * K + kk;
        } else if (k0 < 768) {
            ph = A1h; pl = A1l; aoff = (size_t)(rowStart + ldRow) * 768 + kk;
        } else {
            ph = A2h; pl = A2l; aoff = (size_t)(rowStart + ldRow) * 768 + (kk - 768);
        }
        cp_async16(base + so0, ph + aoff);
        cp_async16(base + so1, ph + aoff + 8);
        cp_async16(base + 8192 + so0, pl + aoff);
        cp_async16(base + 8192 + so1, pl + aoff + 8);
        size_t boff = (size_t)(colStart + ldRow) * K + kk;
        cp_async16(base + 16384 + so0, Wh + boff);
        cp_async16(base + 16384 + so1, Wh + boff + 8);
        cp_async16(base + 24576 + so0, Wl + boff);
        cp_async16(base + 24576 + so1, Wl + boff + 8);
    };

    HMMA_MAINLOOP()

    const int g = lane >> 2, q4 = lane & 3;
    #pragma unroll
    for (int nf = 0; nf < 4; nf++) {
        int c = colStart + wn + 8 * nf + 2 * q4;
        float bx = bias[c], by = bias[c + 1];
        #pragma unroll
        for (int mf = 0; mf < 4; mf++) {
            int r0 = rowStart + wm + 16 * mf + g;
            float v0 = acc[mf][nf][0] + bx;
            float v1 = acc[mf][nf][1] + by;
            float v2 = acc[mf][nf][2] + bx;
            float v3 = acc[mf][nf][3] + by;
            if (EPI == 0 || EPI == 6) {
                *(float2*)(C + (size_t)r0 * 768 + c) = make_float2(v0, v1);
                *(float2*)(C + (size_t)(r0 + 8) * 768 + c) = make_float2(v2, v3);
                if (EPI == 6) {
                    store_split2(Oh, Ol, (size_t)r0 * 768 + c, v0, v1);
                    store_split2(Oh, Ol, (size_t)(r0 + 8) * 768 + c, v2, v3);
                }
            } else { // silu + split
                v0 *= 1.f / (1.f + __expf(-v0));
                v1 *= 1.f / (1.f + __expf(-v1));
                v2 *= 1.f / (1.f + __expf(-v2));
                v3 *= 1.f / (1.f + __expf(-v3));
                store_split2(Oh, Ol, (size_t)r0 * 768 + c, v0, v1);
                store_split2(Oh, Ol, (size_t)(r0 + 8) * 768 + c, v2, v3);
            }
        }
    }
}

// ======================= fused dual-attention QKV =======================
__global__ void __launch_bounds__(256, 2) hmma_qkv2_kernel(
    const bf16* __restrict__ aq0h, const bf16* __restrict__ aq0l,
    const bf16* __restrict__ akv0h, const bf16* __restrict__ akv0l,
    const bf16* __restrict__ aq1h, const bf16* __restrict__ aq1l,
    const bf16* __restrict__ akv1h, const bf16* __restrict__ akv1l,
    const bf16* __restrict__ w0h, const bf16* __restrict__ w0l,
    const bf16* __restrict__ w1h, const bf16* __restrict__ w1l,
    const float* __restrict__ bq0, const float* __restrict__ bk0, const float* __restrict__ bv0,
    const float* __restrict__ bq1, const float* __restrict__ bk1, const float* __restrict__ bv1,
    bf16* __restrict__ q0h, bf16* __restrict__ q0l,
    bf16* __restrict__ k0h, bf16* __restrict__ k0l,
    bf16* __restrict__ vt0h, bf16* __restrict__ vt0l,
    bf16* __restrict__ q1h, bf16* __restrict__ q1l,
    bf16* __restrict__ k1h, bf16* __restrict__ k1l,
    bf16* __restrict__ vt1h, bf16* __restrict__ vt1l)
{
    HMMA_PROLOGUE()
    const int z = blockIdx.z;
    const int att = z / 3, c3 = z - att * 3;
    const bf16* Ah = (c3 == 0) ? (att ? aq1h : aq0h) : (att ? akv1h : akv0h);
    const bf16* Al = (c3 == 0) ? (att ? aq1l : aq0l) : (att ? akv1l : akv0l);
    const bf16* Wh = (att ? w1h : w0h) + (size_t)c3 * WSZ;
    const bf16* Wl = (att ? w1l : w0l) + (size_t)c3 * WSZ;
    const float* bias = att ? (c3 == 0 ? bq1 : c3 == 1 ? bk1 : bv1)
                            : (c3 == 0 ? bq0 : c3 == 1 ? bk0 : bv0);
    bf16* Oh = att ? (c3 == 0 ? q1h : c3 == 1 ? k1h : vt1h)
                   : (c3 == 0 ? q0h : c3 == 1 ? k0h : vt0h);
    bf16* Ol = att ? (c3 == 0 ? q1l : c3 == 1 ? k1l : vt1l)
                   : (c3 == 0 ? q0l : c3 == 1 ? k0l : vt0l);
    const float qs = (c3 == 0) ? 8.f : 1.f;

    const int NIT = 24;
    auto loadTile = [&](int buf, int k0) {
        uint32_t base = sb + buf * 32768;
        int kk = k0 + ldC0 * 8;
        size_t aoff = (size_t)(rowStart + ldRow) * 768 + kk;
        cp_async16(base + so0, Ah + aoff);
        cp_async16(base + so1, Ah + aoff + 8);
        cp_async16(base + 8192 + so0, Al + aoff);
        cp_async16(base + 8192 + so1, Al + aoff + 8);
        size_t boff = (size_t)(colStart + ldRow) * 768 + kk;
        cp_async16(base + 16384 + so0, Wh + boff);
        cp_async16(base + 16384 + so1, Wh + boff + 8);
        cp_async16(base + 24576 + so0, Wl + boff);
        cp_async16(base + 24576 + so1, Wl + boff + 8);
    };
    HMMA_MAINLOOP()
    QKV_EPILOGUE(c3 == 2, qs)
}

// single-attention QKV (stage 3)
__global__ void __launch_bounds__(256, 2) hmma_qkv_kernel(
    const bf16* __restrict__ Aqh, const bf16* __restrict__ Aql,
    const bf16* __restrict__ Akvh, const bf16* __restrict__ Akvl,
    const bf16* __restrict__ Wbh, const bf16* __restrict__ Wbl,
    const float* __restrict__ bq, const float* __restrict__ bk, const float* __restrict__ bv,
    bf16* __restrict__ Qh, bf16* __restrict__ Ql2,
    bf16* __restrict__ Kh, bf16* __restrict__ Kl,
    bf16* __restrict__ Vth, bf16* __restrict__ Vtl)
{
    HMMA_PROLOGUE()
    const int z = blockIdx.z;
    const bf16* Ah = (z == 0) ? Aqh : Akvh;
    const bf16* Al = (z == 0) ? Aql : Akvl;
    const bf16* Wh = Wbh + (size_t)z * WSZ;
    const bf16* Wl = Wbl + (size_t)z * WSZ;
    const float* bias = (z == 0) ? bq : (z == 1) ? bk : bv;
    bf16* Oh = (z == 0) ? Qh : (z == 1) ? Kh : Vth;
    bf16* Ol = (z == 0) ? Ql2 : (z == 1) ? Kl : Vtl;
    const float qs = (z == 0) ? 8.f : 1.f;

    const int NIT = 24;
    auto loadTile = [&](int buf, int k0) {
        uint32_t base = sb + buf * 32768;
        int kk = k0 + ldC0 * 8;
        size_t aoff = (size_t)(rowStart + ldRow) * 768 + kk;
        cp_async16(base + so0, Ah + aoff);
        cp_async16(base + so1, Ah + aoff + 8);
        cp_async16(base + 8192 + so0, Al + aoff);
        cp_async16(base + 8192 + so1, Al + aoff + 8);
        size_t boff = (size_t)(colStart + ldRow) * 768 + kk;
        cp_async16(base + 16384 + so0, Wh + boff);
        cp_async16(base + 16384 + so1, Wh + boff + 8);
        cp_async16(base + 24576 + so0, Wl + boff);
        cp_async16(base + 24576 + so1, Wl + boff + 8);
    };
    HMMA_MAINLOOP()
    QKV_EPILOGUE(z == 2, qs)
}

// ======================= fused dual score (Q pre-scaled by 8) =======================
__global__ void __launch_bounds__(256, 2) hmma_score2_kernel(
    const bf16* __restrict__ q0h, const bf16* __restrict__ q0l,
    const bf16* __restrict__ k0h, const bf16* __restrict__ k0l,
    const bf16* __restrict__ q1h, const bf16* __restrict__ q1l,
    const bf16* __restrict__ k1h, const bf16* __restrict__ k1l,
    float* __restrict__ Sc)
{
    HMMA_PROLOGUE()
    const int z = blockIdx.z;
    const int att = z >> 5, b = z & 31;
    const bf16* Qh = att ? q1h : q0h;
    const bf16* Ql = att ? q1l : q0l;
    const bf16* Kh = att ? k1h : k0h;
    const bf16* Kl = att ? k1l : k0l;

    const int NIT = 24;
    auto loadTile = [&](int buf, int k0) {
        uint32_t base = sb + buf * 32768;
        int kk = k0 + ldC0 * 8;
        size_t aoff = (size_t)(b * 512 + rowStart + ldRow) * 768 + kk;
        size_t boff = (size_t)(b * 512 + colStart + ldRow) * 768 + kk;
        cp_async16(base + so0, Qh + aoff);
        cp_async16(base + so1, Qh + aoff + 8);
        cp_async16(base + 8192 + so0, Ql + aoff);
        cp_async16(base + 8192 + so1, Ql + aoff + 8);
        cp_async16(base + 16384 + so0, Kh + boff);
        cp_async16(base + 16384 + so1, Kh + boff + 8);
        cp_async16(base + 24576 + so0, Kl + boff);
        cp_async16(base + 24576 + so1, Kl + boff + 8);
    };
    HMMA_MAINLOOP()

    float* C = Sc + (size_t)z * 262144;
    const int g = lane >> 2, q4 = lane & 3;
    #pragma unroll
    for (int nf = 0; nf < 4; nf++) {
        int c = colStart + wn + 8 * nf + 2 * q4;
        #pragma unroll
        for (int mf = 0; mf < 4; mf++) {
            int r0 = rowStart + wm + 16 * mf + g;
            *(float2*)(C + (size_t)r0 * 512 + c) =
                make_float2(acc[mf][nf][0], acc[mf][nf][1]);
            *(float2*)(C + (size_t)(r0 + 8) * 512 + c) =
                make_float2(acc[mf][nf][2], acc[mf][nf][3]);
        }
    }
}

// single-attention score (stage 3, H heads; Q pre-scaled by 8)
__global__ void __launch_bounds__(256, 2) hmma_score_kernel(
    const bf16* __restrict__ Qh, const bf16* __restrict__ Ql,
    const bf16* __restrict__ Kh, const bf16* __restrict__ Kl,
    float* __restrict__ Sc, int H, int hd)
{
    HMMA_PROLOGUE()
    const int z = blockIdx.z, b = z / H, h = z - b * H;
    const int NIT = hd / 32;
    auto loadTile = [&](int buf, int k0) {
        uint32_t base = sb + buf * 32768;
        int kk = k0 + ldC0 * 8;
        size_t aoff = (size_t)(b * 512 + rowStart + ldRow) * 768 + h * hd + kk;
        size_t boff = (size_t)(b * 512 + colStart + ldRow) * 768 + h * hd + kk;
        cp_async16(base + so0, Qh + aoff);
        cp_async16(base + so1, Qh + aoff + 8);
        cp_async16(base + 8192 + so0, Ql + aoff);
        cp_async16(base + 8192 + so1, Ql + aoff + 8);
        cp_async16(base + 16384 + so0, Kh + boff);
        cp_async16(base + 16384 + so1, Kh + boff + 8);
        cp_async16(base + 24576 + so0, Kl + boff);
        cp_async16(base + 24576 + so1, Kl + boff + 8);
    };
    HMMA_MAINLOOP()

    float* C = Sc + (size_t)z * 262144;
    const int g = lane >> 2, q4 = lane & 3;
    #pragma unroll
    for (int nf = 0; nf < 4; nf++) {
        int c = colStart + wn + 8 * nf + 2 * q4;
        #pragma unroll
        for (int mf = 0; mf < 4; mf++) {
            int r0 = rowStart + wm + 16 * mf + g;
            *(float2*)(C + (size_t)r0 * 512 + c) =
                make_float2(acc[mf][nf][0], acc[mf][nf][1]);
            *(float2*)(C + (size_t)(r0 + 8) * 512 + c) =
                make_float2(acc[mf][nf][2], acc[mf][nf][3]);
        }
    }
}

// ======================= fused dual PV =======================
__global__ void __launch_bounds__(256, 2) hmma_pv2_kernel(
    const bf16* __restrict__ Ph, const bf16* __restrict__ Pl,
    const bf16* __restrict__ vt0h, const bf16* __restrict__ vt0l,
    const bf16* __restrict__ vt1h, const bf16* __restrict__ vt1l,
    bf16* __restrict__ o0h, bf16* __restrict__ o0l,
    bf16* __restrict__ o1h, bf16* __restrict__ o1l)
{
    HMMA_PROLOGUE()
    const int z = blockIdx.z;
    const int att = z >> 5, b = z & 31;
    const bf16* Vth = att ? vt1h : vt0h;
    const bf16* Vtl = att ? vt1l : vt0l;
    bf16* Oh = att ? o1h : o0h;
    bf16* Ol = att ? o1l : o0l;

    const int NIT = 16;
    auto loadTile = [&](int buf, int k0) {
        uint32_t base = sb + buf * 32768;
        int kk = k0 + ldC0 * 8;
        size_t aoff = (size_t)z * 262144 + (size_t)(rowStart + ldRow) * 512 + kk;
        size_t boff = (size_t)(b * 768 + colStart + ldRow) * 512 + kk;
        cp_async16(base + so0, Ph + aoff);
        cp_async16(base + so1, Ph + aoff + 8);
        cp_async16(base + 8192 + so0, Pl + aoff);
        cp_async16(base + 8192 + so1, Pl + aoff + 8);
        cp_async16(base + 16384 + so0, Vth + boff);
        cp_async16(base + 16384 + so1, Vth + boff + 8);
        cp_async16(base + 24576 + so0, Vtl + boff);
        cp_async16(base + 24576 + so1, Vtl + boff + 8);
    };
    HMMA_MAINLOOP()

    const int g = lane >> 2, q4 = lane & 3;
    #pragma unroll
    for (int nf = 0; nf < 4; nf++) {
        int c = colStart + wn + 8 * nf + 2 * q4;
        #pragma unroll
        for (int mf = 0; mf < 4; mf++) {
            int r0 = b * 512 + rowStart + wm + 16 * mf + g;
            store_split2(Oh, Ol, (size_t)r0 * 768 + c, acc[mf][nf][0], acc[mf][nf][1]);
            store_split2(Oh, Ol, (size_t)(r0 + 8) * 768 + c, acc[mf][nf][2], acc[mf][nf][3]);
        }
    }
}

// stage-3 PV with native 96-wide tiles (hd=96): warp col tile = 24, 3 n-frags
__global__ void __launch_bounds__(256, 2) hmma_pv96_kernel(
    const bf16* __restrict__ Ph, const bf16* __restrict__ Pl,
    const bf16* __restrict__ Vth, const bf16* __restrict__ Vtl,
    bf16* __restrict__ Oh, bf16* __restrict__ Ol)
{
    extern __shared__ char smem[];
    uint32_t sb = smem_u32(smem);
    const int tid = threadIdx.x;
    const int H = 8, hd = 96;
    const int z = blockIdx.z, b = z / H, h = z - b * H;
    const int rowStart = blockIdx.y * 128;
    const int warp = tid >> 5, lane = tid & 31;
    const int wm = (warp & 1) * 64, wn = (warp >> 1) * 24;
    const int ldRow = tid >> 1;
    const int ldC0 = (tid & 1) * 2;
    const uint32_t so0 = swz(ldRow, ldC0);
    const uint32_t so1 = swz(ldRow, ldC0 + 1);
    const int rA = lane & 15, khA = lane >> 4;
    const int rB = lane & 7, khB = (lane >> 3) & 1;
    float acc[4][3][4];
    #pragma unroll
    for (int i = 0; i < 4; i++)
        #pragma unroll
        for (int j = 0; j < 3; j++)
            #pragma unroll
            for (int c = 0; c < 4; c++) acc[i][j][c] = 0.f;

    const int NIT = 16;
    auto loadTile = [&](int buf, int k0) {
        uint32_t base = sb + buf * 32768;
        int kk = k0 + ldC0 * 8;
        size_t aoff = (size_t)z * 262144 + (size_t)(rowStart + ldRow) * 512 + kk;
        size_t boff = (size_t)(b * 768 + h * hd + ldRow) * 512 + kk;   // rows 96..127 pad-safe
        cp_async16(base + so0, Ph + aoff);
        cp_async16(base + so1, Ph + aoff + 8);
        cp_async16(base + 8192 + so0, Pl + aoff);
        cp_async16(base + 8192 + so1, Pl + aoff + 8);
        cp_async16(base + 16384 + so0, Vth + boff);
        cp_async16(base + 16384 + so1, Vth + boff + 8);
        cp_async16(base + 24576 + so0, Vtl + boff);
        cp_async16(base + 24576 + so1, Vtl + boff + 8);
    };
    HMMA_MAINLOOP96()

    const int g = lane >> 2, q4 = lane & 3;
    #pragma unroll
    for (int nf = 0; nf < 3; nf++) {
        int c = h * hd + wn + 8 * nf + 2 * q4;
        #pragma unroll
        for (int mf = 0; mf < 4; mf++) {
            int r0 = b * 512 + rowStart + wm + 16 * mf + g;
            store_split2(Oh, Ol, (size_t)r0 * 768 + c, acc[mf][nf][0], acc[mf][nf][1]);
            store_split2(Oh, Ol, (size_t)(r0 + 8) * 768 + c, acc[mf][nf][2], acc[mf][nf][3]);
        }
    }
}

// ======================= host =======================
extern "C" void kernel_launch(void* const* d_in, const int* in_sizes, int n_in,
                              void* d_out, int out_size)
{
    (void)n_in; (void)out_size;
    const float *text, *vtab, *atab;
    const float *aw[18];
    const float *fcw, *fcb, *f1w, *f1b, *f2w, *f2b, *catw, *catb;
    const int *vid, *aid;

    if (in_sizes[1] == MR) {
        text = (const float*)d_in[0];
        vid  = (const int*)d_in[1];
        aid  = (const int*)d_in[2];
        vtab = (const float*)d_in[3];
        atab = (const float*)d_in[4];
        for (int i = 0; i < 18; i++) aw[i] = (const float*)d_in[5 + i];
        fcw = (const float*)d_in[23]; fcb = (const float*)d_in[24];
        f1w = (const float*)d_in[25]; f1b = (const float*)d_in[26];
        f2w = (const float*)d_in[27]; f2b = (const float*)d_in[28];
        catw = (const float*)d_in[29]; catb = (const float*)d_in[30];
    } else {
        text = (const float*)d_in[0];
        vtab = (const float*)d_in[1];
        atab = (const float*)d_in[2];
        for (int i = 0; i < 18; i++) aw[i] = (const float*)d_in[3 + i];
        fcw = (const float*)d_in[21]; fcb = (const float*)d_in[22];
        f1w = (const float*)d_in[23]; f1b = (const float*)d_in[24];
        f2w = (const float*)d_in[25]; f2b = (const float*)d_in[26];
        catw = (const float*)d_in[27]; catb = (const float*)d_in[28];
        vid  = (const int*)d_in[29];
        aid  = (const int*)d_in[30];
    }

    cudaFuncSetAttribute(hmma_gemm_kernel<0,0>, cudaFuncAttributeMaxDynamicSharedMemorySize, HG_SMEM);
    cudaFuncSetAttribute(hmma_gemm_kernel<5,0>, cudaFuncAttributeMaxDynamicSharedMemorySize, HG_SMEM);
    cudaFuncSetAttribute(hmma_gemm_kernel<6,0>, cudaFuncAttributeMaxDynamicSharedMemorySize, HG_SMEM);
    cudaFuncSetAttribute(hmma_gemm_kernel<0,1>, cudaFuncAttributeMaxDynamicSharedMemorySize, HG_SMEM);
    cudaFuncSetAttribute(hmma_qkv_kernel, cudaFuncAttributeMaxDynamicSharedMemorySize, HG_SMEM);
    cudaFuncSetAttribute(hmma_qkv2_kernel, cudaFuncAttributeMaxDynamicSharedMemorySize, HG_SMEM);
    cudaFuncSetAttribute(hmma_score_kernel, cudaFuncAttributeMaxDynamicSharedMemorySize, HG_SMEM);
    cudaFuncSetAttribute(hmma_score2_kernel, cudaFuncAttributeMaxDynamicSharedMemorySize, HG_SMEM);
    cudaFuncSetAttribute(hmma_pv2_kernel, cudaFuncAttributeMaxDynamicSharedMemorySize, HG_SMEM);
    cudaFuncSetAttribute(hmma_pv96_kernel, cudaFuncAttributeMaxDynamicSharedMemorySize, HG_SMEM);

    float *sc, *F1, *F2, *F3;
    bf16 *wth, *wtl, *cth, *ctl;
    bf16 *spt_h, *spt_l, *sev_h, *sev_l, *sea_h, *sea_l;
    bf16 *sq_h, *sq_l, *sk_h, *sk_l, *svt_h, *svt_l;
    bf16 *sq2_h, *sq2_l, *sk2_h, *sk2_l, *svt2_h, *svt2_l;
    bf16 *sp_h, *sp_l;
    bf16 *s1_h, *s1_l, *s2_h, *s2_l, *s3_h, *s3_l, *s4_h, *s4_l;
    bf16 *c1_h, *c1_l, *c2_h, *c2_l, *c3_h, *c3_l;
    cudaGetSymbolAddress((void**)&sc, g_sc);
    cudaGetSymbolAddress((void**)&F1, g_F1);
    cudaGetSymbolAddress((void**)&F2, g_F2);
    cudaGetSymbolAddress((void**)&F3, g_F3);
    cudaGetSymbolAddress((void**)&wth, g_wth);
    cudaGetSymbolAddress((void**)&wtl, g_wtl);
    cudaGetSymbolAddress((void**)&cth, g_cth);
    cudaGetSymbolAddress((void**)&ctl, g_ctl);
    cudaGetSymbolAddress((void**)&spt_h, g_spt_h); cudaGetSymbolAddress((void**)&spt_l, g_spt_l);
    cudaGetSymbolAddress((void**)&sev_h, g_sev_h); cudaGetSymbolAddress((void**)&sev_l, g_sev_l);
    cudaGetSymbolAddress((void**)&sea_h, g_sea_h); cudaGetSymbolAddress((void**)&sea_l, g_sea_l);
    cudaGetSymbolAddress((void**)&sq_h, g_sq_h);   cudaGetSymbolAddress((void**)&sq_l, g_sq_l);
    cudaGetSymbolAddress((void**)&sk_h, g_sk_h);   cudaGetSymbolAddress((void**)&sk_l, g_sk_l);
    cudaGetSymbolAddress((void**)&svt_h, g_svt_h); cudaGetSymbolAddress((void**)&svt_l, g_svt_l);
    cudaGetSymbolAddress((void**)&sq2_h, g_sq2_h); cudaGetSymbolAddress((void**)&sq2_l, g_sq2_l);
    cudaGetSymbolAddress((void**)&sk2_h, g_sk2_h); cudaGetSymbolAddress((void**)&sk2_l, g_sk2_l);
    cudaGetSymbolAddress((void**)&svt2_h, g_svt2_h); cudaGetSymbolAddress((void**)&svt2_l, g_svt2_l);
    cudaGetSymbolAddress((void**)&sp_h, g_sp_h);   cudaGetSymbolAddress((void**)&sp_l, g_sp_l);
    cudaGetSymbolAddress((void**)&s1_h, g_s1_h);   cudaGetSymbolAddress((void**)&s1_l, g_s1_l);
    cudaGetSymbolAddress((void**)&s2_h, g_s2_h);   cudaGetSymbolAddress((void**)&s2_l, g_s2_l);
    cudaGetSymbolAddress((void**)&s3_h, g_s3_h);   cudaGetSymbolAddress((void**)&s3_l, g_s3_l);
    cudaGetSymbolAddress((void**)&s4_h, g_s4_h);   cudaGetSymbolAddress((void**)&s4_l, g_s4_l);
    cudaGetSymbolAddress((void**)&c1_h, g_c1_h);   cudaGetSymbolAddress((void**)&c1_l, g_c1_l);
    cudaGetSymbolAddress((void**)&c2_h, g_c2_h);   cudaGetSymbolAddress((void**)&c2_l, g_c2_l);
    cudaGetSymbolAddress((void**)&c3_h, g_c3_h);   cudaGetSymbolAddress((void**)&c3_l, g_c3_l);

    const int EW = (NEL + 255) / 256;
    const int SW = (NEL / 2 + 255) / 256;
    const dim3 gHG(6, 128);

    // -------- weight prep --------
    const float* wsrc[12] = { aw[0], aw[2], aw[4], aw[6], aw[8], aw[10],
                              aw[12], aw[14], aw[16], fcw, f1w, f2w };
    for (int i = 0; i < 12; i++)
        wsplit_kernel<<<dim3(24, 24), 256>>>(wsrc[i], wth + (size_t)i * WSZ, wtl + (size_t)i * WSZ, 768);
    wsplit_kernel<<<dim3(48, 24), 256>>>(catw, cth, ctl, 1536);

    auto GEMM_F = [&](const bf16* Ah, const bf16* Al, int wi, const float* bi, float* Cc) {
        hmma_gemm_kernel<0,0><<<gHG, 256, HG_SMEM>>>(Ah, Al, nullptr, nullptr,
            wth + (size_t)wi * WSZ, wtl + (size_t)wi * WSZ, bi, Cc, nullptr, nullptr, 768);
    };
    auto GEMM_FS = [&](const bf16* Ah, const bf16* Al, int wi, const float* bi, float* Cc,
                       bf16* oh, bf16* ol) {
        hmma_gemm_kernel<6,0><<<gHG, 256, HG_SMEM>>>(Ah, Al, nullptr, nullptr,
            wth + (size_t)wi * WSZ, wtl + (size_t)wi * WSZ, bi, Cc, oh, ol, 768);
    };
    auto GEMM_SILU = [&](const bf16* Ah, const bf16* Al, int wi, const float* bi, bf16* oh, bf16* ol) {
        hmma_gemm_kernel<5,0><<<gHG, 256, HG_SMEM>>>(Ah, Al, nullptr, nullptr,
            wth + (size_t)wi * WSZ, wtl + (size_t)wi * WSZ, bi, nullptr, oh, ol, 768);
    };
    auto CATGEMM = [&](const bf16* A1h, const bf16* A1l, const bf16* A2h, const bf16* A2l,
                       const float* bi, float* Cc) {
        hmma_gemm_kernel<0,1><<<gHG, 256, HG_SMEM>>>(A1h, A1l, A2h, A2l, cth, ctl, bi, Cc,
                                                     nullptr, nullptr, 1536);
    };
    auto ATT2 = [&](const bf16* q0h_, const bf16* q0l_, const bf16* kv0h_, const bf16* kv0l_,
                    const bf16* q1h_, const bf16* q1l_, const bf16* kv1h_, const bf16* kv1l_,
                    bf16* o0h, bf16* o0l, bf16* o1h, bf16* o1l) {
        hmma_qkv2_kernel<<<dim3(6, 128, 6), 256, HG_SMEM>>>(
            q0h_, q0l_, kv0h_, kv0l_, q1h_, q1l_, kv1h_, kv1l_,
            wth, wtl, wth + 3 * (size_t)WSZ, wtl + 3 * (size_t)WSZ,
            aw[1], aw[3], aw[5], aw[7], aw[9], aw[11],
            sq_h, sq_l, sk_h, sk_l, svt_h, svt_l,
            sq2_h, sq2_l, sk2_h, sk2_l, svt2_h, svt2_l);
        hmma_score2_kernel<<<dim3(4, 4, 64), 256, HG_SMEM>>>(
            sq_h, sq_l, sk_h, sk_l, sq2_h, sq2_l, sk2_h, sk2_l, sc);
        softmax_split_kernel<<<2 * MR, 256>>>(sc, sp_h, sp_l);
        hmma_pv2_kernel<<<dim3(6, 4, 64), 256, HG_SMEM>>>(
            sp_h, sp_l, svt_h, svt_l, svt2_h, svt2_l, o0h, o0l, o1h, o1l);
    };
    auto FFN = [&](float* x) {   // scratch: c1, c2 only
        gate_split_kernel<<<MR, 256>>>(x, c1_h, c1_l);
        GEMM_SILU(c1_h, c1_l, 10, f1b, c2_h, c2_l);
        GEMM_F(c2_h, c2_l, 11, f2b, x);
    };

    // -------- forward --------
    asplit_kernel<<<SW, 256>>>(text, spt_h, spt_l);
    embed_split_kernel<<<EW, 256>>>(vtab, vid, sev_h, sev_l);
    embed_split_kernel<<<EW, 256>>>(atab, aid, sea_h, sea_l);

    // stage 1: visual_=hv(text,emb_v), acoustic_=ha(text,emb_a)
    ATT2(spt_h, spt_l, sev_h, sev_l, spt_h, spt_l, sea_h, sea_l, s1_h, s1_l, s2_h, s2_l);
    CATGEMM(s1_h, s1_l, s2_h, s2_l, catb, F1);
    // FFN(F1) with fused split of final output into DEDICATED c3 (survives stage 2)
    gate_split_kernel<<<MR, 256>>>(F1, c1_h, c1_l);
    GEMM_SILU(c1_h, c1_l, 10, f1b, c2_h, c2_l);
    GEMM_FS(c2_h, c2_l, 11, f2b, F1, c3_h, c3_l);   // F1 fp32 + split -> c3

    // stage 2: v=hv(visual_,acoustic_), a=ha(acoustic_,visual_)
    ATT2(s1_h, s1_l, s2_h, s2_l, s2_h, s2_l, s1_h, s1_l, s3_h, s3_l, s4_h, s4_l);
    CATGEMM(s3_h, s3_l, s4_h, s4_l, catb, F2);
    FFN(F2);   // uses c1/c2 — c3 untouched

    // stage 3: F3 = mh8(F1, text) @ fcw + fcb, then FFN   (c3 = split(F1))
    hmma_qkv_kernel<<<dim3(6, 128, 3), 256, HG_SMEM>>>(
        c3_h, c3_l, spt_h, spt_l,
        wth + 6 * (size_t)WSZ, wtl + 6 * (size_t)WSZ,
        aw[13], aw[15], aw[17], sq_h, sq_l, sk_h, sk_l, svt_h, svt_l);
    hmma_score_kernel<<<dim3(4, 4, 256), 256, HG_SMEM>>>(sq_h, sq_l, sk_h, sk_l, sc, 8, 96);
    softmax_split_kernel<<<BB * 8 * SS, 256>>>(sc, sp_h, sp_l);
    hmma_pv96_kernel<<<dim3(1, 4, 256), 256, HG_SMEM>>>(sp_h, sp_l, svt_h, svt_l, c2_h, c2_l);
    GEMM_F(c2_h, c2_l, 9, fcb, F3);
    FFN(F3);

    // out = gate(text + F1 + F2 + F3)
    gate4_kernel<<<MR, 256>>>(text, F1, F2, F3, (float*)d_out);
}